// round 3
// baseline (speedup 1.0000x reference)
#include <cuda_runtime.h>

#define NB    4
#define QLEN  4096
#define HIDD  1024
#define NHEAD 16
#define HDIM  64
#define TXTN  77
#define IPTN  8
#define CDIM  768
#define ENCR  85   // TXT + IPT

// ---------------- scratch (no allocation allowed) ----------------
__device__ float g_Wq [HIDD*HIDD];
__device__ float g_Wk [CDIM*HIDD];
__device__ float g_Wv [CDIM*HIDD];
__device__ float g_Wo [HIDD*HIDD];
__device__ float g_q  [NB*QLEN*HIDD];
__device__ float g_hid[NB*QLEN*HIDD];
__device__ float g_kk [NB*TXTN*HIDD];
__device__ float g_vv [NB*TXTN*HIDD];
__device__ float g_ipk[NB*IPTN*HIDD];
__device__ float g_ipv[NB*IPTN*HIDD];
__device__ float g_ehs[NB*TXTN*CDIM];
__device__ float g_ip [NB*IPTN*CDIM];
__device__ float g_ipkS[NB*HIDD];
__device__ float g_w  [NB*QLEN];
__device__ float g_mm [2*NB];

// ---------------- fold rank-4 LoRA into weight ----------------
__global__ void fuse_w_kernel(const float* __restrict__ W,
                              const float* __restrict__ down,
                              const float* __restrict__ up,
                              float* __restrict__ out, int K)
{
    int idx = blockIdx.x * 256 + threadIdx.x;
    if (idx >= K * HIDD) return;
    int r = idx >> 10, c = idx & 1023;
    float acc = W[idx];
#pragma unroll
    for (int j = 0; j < 4; j++)
        acc = fmaf(down[r*4 + j], up[j*HIDD + c], acc);
    out[idx] = acc;
}

// ---------------- pack encoder slices contiguous ----------------
__global__ void pack_enc_kernel(const float* __restrict__ enc,
                                float* __restrict__ ehs,
                                float* __restrict__ ipb)
{
    int idx = blockIdx.x * 256 + threadIdx.x;
    const int n1 = NB*TXTN*CDIM;
    const int n2 = NB*IPTN*CDIM;
    if (idx < n1) {
        int b = idx / (TXTN*CDIM);
        int rem = idx - b*(TXTN*CDIM);
        int t = rem / CDIM, c = rem - t*CDIM;
        ehs[idx] = enc[((size_t)b*ENCR + t)*CDIM + c];
    } else if (idx < n1 + n2) {
        int k = idx - n1;
        int b = k / (IPTN*CDIM);
        int rem = k - b*(IPTN*CDIM);
        int t = rem / CDIM, c = rem - t*CDIM;
        ipb[k] = enc[((size_t)b*ENCR + TXTN + t)*CDIM + c];
    }
}

// ---------------- tiled fp32 GEMM: C[M,N] = A[M,K] @ B[K,N] (+bias) ----------------
// BM=BN=128, BK=8, 256 threads, 8x8 per thread. Row-guarded for M not mult of 128.
// N must be a multiple of 128, K a multiple of 8 (true for all calls here).
__global__ __launch_bounds__(256) void sgemm128(
    const float* __restrict__ A, const float* __restrict__ B,
    float* __restrict__ C, const float* __restrict__ bias,
    int M, int N, int K)
{
    __shared__ float As[8][128];
    __shared__ float Bs[8][128];
    const int tid = threadIdx.x;
    const int bx = blockIdx.x, by = blockIdx.y;
    const int tcol = tid & 15, trow = tid >> 4;
    const int a_row = tid >> 1, a_col = (tid & 1) << 2;
    const int b_row = tid >> 5, b_col = (tid & 31) << 2;

    const float* Ab = A + (size_t)by * 128 * K;
    const float* Bb = B + bx * 128;
    const int arow_g = by * 128 + a_row;
    const bool aval = (arow_g < M);

    float acc[8][8];
#pragma unroll
    for (int i = 0; i < 8; i++)
#pragma unroll
        for (int j = 0; j < 8; j++) acc[i][j] = 0.f;

    for (int k0 = 0; k0 < K; k0 += 8) {
        float4 av = aval ? *(const float4*)(Ab + (size_t)a_row*K + k0 + a_col)
                         : make_float4(0.f, 0.f, 0.f, 0.f);
        As[a_col + 0][a_row] = av.x;
        As[a_col + 1][a_row] = av.y;
        As[a_col + 2][a_row] = av.z;
        As[a_col + 3][a_row] = av.w;
        float4 bv = *(const float4*)(Bb + (size_t)(k0 + b_row)*N + b_col);
        *(float4*)&Bs[b_row][b_col] = bv;
        __syncthreads();
#pragma unroll
        for (int kk = 0; kk < 8; kk++) {
            float ra[8], rb[8];
            *(float4*)(ra)     = *(const float4*)&As[kk][trow*8];
            *(float4*)(ra + 4) = *(const float4*)&As[kk][trow*8 + 4];
            *(float4*)(rb)     = *(const float4*)&Bs[kk][tcol*8];
            *(float4*)(rb + 4) = *(const float4*)&Bs[kk][tcol*8 + 4];
#pragma unroll
            for (int i = 0; i < 8; i++)
#pragma unroll
                for (int j = 0; j < 8; j++)
                    acc[i][j] = fmaf(ra[i], rb[j], acc[i][j]);
        }
        __syncthreads();
    }

    const int rb0 = by*128 + trow*8;
    const int cb0 = bx*128 + tcol*8;
#pragma unroll
    for (int i = 0; i < 8; i++) {
        int r = rb0 + i;
        if (r >= M) continue;
#pragma unroll
        for (int j = 0; j < 8; j += 4) {
            float4 v = make_float4(acc[i][j], acc[i][j+1], acc[i][j+2], acc[i][j+3]);
            if (bias) {
                v.x += bias[cb0 + j + 0];
                v.y += bias[cb0 + j + 1];
                v.z += bias[cb0 + j + 2];
                v.w += bias[cb0 + j + 3];
            }
            *(float4*)(C + (size_t)r*N + cb0 + j) = v;
        }
    }
}

// ---------------- ipk token-sum: [B,8,1024] -> [B,1024] ----------------
__global__ void ipksum_kernel(const float* __restrict__ ipk, float* __restrict__ out)
{
    int idx = blockIdx.x * 256 + threadIdx.x;
    if (idx >= NB * HIDD) return;
    int b = idx >> 10, j = idx & 1023;
    float s = 0.f;
#pragma unroll
    for (int t = 0; t < IPTN; t++)
        s += ipk[((size_t)b*IPTN + t)*HIDD + j];
    out[idx] = s;
}

// ---------------- w[b,q] = scale * dot(q_full, ipkSum) ----------------
__global__ __launch_bounds__(256) void wsum_kernel(const float* __restrict__ qb,
                                                   const float* __restrict__ ipkS,
                                                   float* __restrict__ w)
{
    __shared__ float sk[HIDD];
    const int row0 = blockIdx.x * 8;          // 8 rows/block, same batch
    const int b = row0 / QLEN;
    for (int i = threadIdx.x; i < HIDD; i += 256) sk[i] = ipkS[b*HIDD + i];
    __syncthreads();
    const int warp = threadIdx.x >> 5, lane = threadIdx.x & 31;
    const int row = row0 + warp;
    const float* qr = qb + (size_t)row * HIDD;
    float s = 0.f;
#pragma unroll
    for (int i = 0; i < 32; i++)
        s = fmaf(qr[lane + 32*i], sk[lane + 32*i], s);
#pragma unroll
    for (int off = 16; off > 0; off >>= 1)
        s += __shfl_xor_sync(0xffffffffu, s, off);
    if (lane == 0) w[row] = 0.125f * s;
}

// ---------------- per-batch min/max of w ----------------
__global__ void minmax_kernel(const float* __restrict__ w, float* __restrict__ mm)
{
    __shared__ float smn[256], smx[256];
    const int b = blockIdx.x, tid = threadIdx.x;
    float mn = 1e30f, mx = -1e30f;
    for (int i = tid; i < QLEN; i += 256) {
        float v = w[b*QLEN + i];
        mn = fminf(mn, v); mx = fmaxf(mx, v);
    }
    smn[tid] = mn; smx[tid] = mx;
    __syncthreads();
    for (int s = 128; s > 0; s >>= 1) {
        if (tid < s) {
            smn[tid] = fminf(smn[tid], smn[tid + s]);
            smx[tid] = fmaxf(smx[tid], smx[tid + s]);
        }
        __syncthreads();
    }
    if (tid == 0) { mm[2*b] = smn[0]; mm[2*b + 1] = smx[0]; }
}

// ---------------- fused attention: text softmax-attn + IP attn + aw combine ----------------
// block = 128 threads, one thread per q row; block handles (b, h, 128 q rows)
__global__ __launch_bounds__(128) void attn_kernel(
    const float* __restrict__ qb,   // [B,Q,1024]
    const float* __restrict__ kk,   // [B,77,1024]
    const float* __restrict__ vv,
    const float* __restrict__ ipk,  // [B,8,1024]
    const float* __restrict__ ipv,
    const float* __restrict__ wbuf, // [B,Q]
    const float* __restrict__ mm,   // [B][min,max]
    float* __restrict__ hid)        // [B,Q,1024]
{
    __shared__ float smem[TXTN*HDIM*2 + IPTN*HDIM*2];   // 10880 floats = 43520 B
    float* sK  = smem;
    float* sV  = smem + TXTN*HDIM;
    float* sIK = smem + 2*TXTN*HDIM;
    float* sIV = sIK + IPTN*HDIM;

    const int tid = threadIdx.x;
    const int b = blockIdx.z, h = blockIdx.y, q0 = blockIdx.x * 128;

    const size_t kvbase = ((size_t)b*TXTN)*HIDD + h*HDIM;
    for (int i = tid; i < TXTN*HDIM; i += 128) {
        int t = i >> 6, d = i & 63;
        sK[i] = kk[kvbase + (size_t)t*HIDD + d];
        sV[i] = vv[kvbase + (size_t)t*HIDD + d];
    }
    const size_t ipbase = ((size_t)b*IPTN)*HIDD + h*HDIM;
    for (int i = tid; i < IPTN*HDIM; i += 128) {
        int t = i >> 6, d = i & 63;
        sIK[i] = ipk[ipbase + (size_t)t*HIDD + d];
        sIV[i] = ipv[ipbase + (size_t)t*HIDD + d];
    }
    __syncthreads();

    const int qi = q0 + tid;                       // q index within batch
    float4 q4[16];
    const float4* qp = (const float4*)(qb + ((size_t)b*QLEN + qi)*HIDD + h*HDIM);
#pragma unroll
    for (int i = 0; i < 16; i++) q4[i] = qp[i];

    // ---- text attention, online softmax with lazy rescale ----
    float m = -1e30f, l = 0.f;
    float4 o4[16];
#pragma unroll
    for (int i = 0; i < 16; i++) o4[i] = make_float4(0.f, 0.f, 0.f, 0.f);

    for (int t = 0; t < TXTN; t++) {
        const float4* kp = (const float4*)(sK + t*HDIM);
        float s = 0.f;
#pragma unroll
        for (int i = 0; i < 16; i++) {
            float4 kv = kp[i];
            s = fmaf(q4[i].x, kv.x, s); s = fmaf(q4[i].y, kv.y, s);
            s = fmaf(q4[i].z, kv.z, s); s = fmaf(q4[i].w, kv.w, s);
        }
        s *= 0.125f;
        if (s > m) {
            float c = __expf(m - s);
            l *= c;
#pragma unroll
            for (int i = 0; i < 16; i++) {
                o4[i].x *= c; o4[i].y *= c; o4[i].z *= c; o4[i].w *= c;
            }
            m = s;
        }
        float p = __expf(s - m);
        l += p;
        const float4* vp = (const float4*)(sV + t*HDIM);
#pragma unroll
        for (int i = 0; i < 16; i++) {
            float4 v = vp[i];
            o4[i].x = fmaf(p, v.x, o4[i].x); o4[i].y = fmaf(p, v.y, o4[i].y);
            o4[i].z = fmaf(p, v.z, o4[i].z); o4[i].w = fmaf(p, v.w, o4[i].w);
        }
    }
    const float inv_l = 1.f / l;

    // ---- IP attention (8 tokens, bbox mask) ----
    float sip[IPTN];
#pragma unroll
    for (int t = 0; t < IPTN; t++) {
        const float4* kp = (const float4*)(sIK + t*HDIM);
        float s = 0.f;
#pragma unroll
        for (int i = 0; i < 16; i++) {
            float4 kv = kp[i];
            s = fmaf(q4[i].x, kv.x, s); s = fmaf(q4[i].y, kv.y, s);
            s = fmaf(q4[i].z, kv.z, s); s = fmaf(q4[i].w, kv.w, s);
        }
        sip[t] = s * 0.125f;
    }
    const int gr = qi >> 6, gc = qi & 63;
    const int region = (gr < 32) ? ((gc < 32) ? 0 : -1)
                                 : ((gc >= 32) ? 1 : -1);
    if (region == 0) { sip[4] = sip[5] = sip[6] = sip[7] = -1e30f; }
    else if (region == 1) { sip[0] = sip[1] = sip[2] = sip[3] = -1e30f; }

    float m2 = -1e30f;
#pragma unroll
    for (int t = 0; t < IPTN; t++) m2 = fmaxf(m2, sip[t]);
    float p2[IPTN], sum2 = 0.f;
#pragma unroll
    for (int t = 0; t < IPTN; t++) { p2[t] = __expf(sip[t] - m2); sum2 += p2[t]; }

    // ---- aw gate ----
    const float wv  = wbuf[b*QLEN + qi];
    const float wmn = mm[2*b], wmx = mm[2*b + 1];
    float aw = (wv - wmn) / (wmx - wmn);
    aw = (aw < 0.3f) ? 0.f : aw;
    aw *= 0.5f;
    if (region >= 0) aw = aw * 2.f + 1.f;
    const float coeff = aw / sum2;

#pragma unroll
    for (int i = 0; i < 16; i++) {
        float4 acc = make_float4(0.f, 0.f, 0.f, 0.f);
#pragma unroll
        for (int t = 0; t < IPTN; t++) {
            float4 v = ((const float4*)(sIV + t*HDIM))[i];
            acc.x = fmaf(p2[t], v.x, acc.x); acc.y = fmaf(p2[t], v.y, acc.y);
            acc.z = fmaf(p2[t], v.z, acc.z); acc.w = fmaf(p2[t], v.w, acc.w);
        }
        o4[i].x = o4[i].x * inv_l + coeff * acc.x;
        o4[i].y = o4[i].y * inv_l + coeff * acc.y;
        o4[i].z = o4[i].z * inv_l + coeff * acc.z;
        o4[i].w = o4[i].w * inv_l + coeff * acc.w;
    }

    // ---- stage through smem (stride 68 to dodge bank conflicts), coalesced store ----
    __syncthreads();                // everyone done reading sK/sV/sIK/sIV
    float* so = smem;               // 128*68 = 8704 floats, fits in sK+sV region
#pragma unroll
    for (int i = 0; i < 16; i++)
        *(float4*)(so + tid*68 + i*4) = o4[i];
    __syncthreads();

    float* outp = hid + ((size_t)b*QLEN + q0)*HIDD + h*HDIM;
    for (int i4 = tid; i4 < 128*16; i4 += 128) {
        int r = i4 >> 4, c = i4 & 15;
        float4 v = *(const float4*)(so + r*68 + c*4);
        *(float4*)(outp + (size_t)r*HIDD + c*4) = v;
    }
}

// ---------------- host launcher ----------------
extern "C" void kernel_launch(void* const* d_in, const int* in_sizes, int n_in,
                              void* d_out, int out_size)
{
    const float* hs     = (const float*)d_in[0];
    const float* enc    = (const float*)d_in[1];
    const float* Wq     = (const float*)d_in[2];
    const float* Wk     = (const float*)d_in[3];
    const float* Wv     = (const float*)d_in[4];
    const float* Wo     = (const float*)d_in[5];
    const float* bo     = (const float*)d_in[6];
    const float* q_down = (const float*)d_in[7];
    const float* q_up   = (const float*)d_in[8];
    const float* k_down = (const float*)d_in[9];
    const float* k_up   = (const float*)d_in[10];
    const float* v_down = (const float*)d_in[11];
    const float* v_up   = (const float*)d_in[12];
    const float* o_down = (const float*)d_in[13];
    const float* o_up   = (const float*)d_in[14];
    const float* Wk_ip  = (const float*)d_in[15];
    const float* Wv_ip  = (const float*)d_in[16];
    float* out = (float*)d_out;

    float *pWq, *pWk, *pWv, *pWo, *pq, *phid, *pkk, *pvv, *pipk, *pipv;
    float *pehs, *pip, *pipkS, *pw, *pmm;
    cudaGetSymbolAddress((void**)&pWq,  g_Wq);
    cudaGetSymbolAddress((void**)&pWk,  g_Wk);
    cudaGetSymbolAddress((void**)&pWv,  g_Wv);
    cudaGetSymbolAddress((void**)&pWo,  g_Wo);
    cudaGetSymbolAddress((void**)&pq,   g_q);
    cudaGetSymbolAddress((void**)&phid, g_hid);
    cudaGetSymbolAddress((void**)&pkk,  g_kk);
    cudaGetSymbolAddress((void**)&pvv,  g_vv);
    cudaGetSymbolAddress((void**)&pipk, g_ipk);
    cudaGetSymbolAddress((void**)&pipv, g_ipv);
    cudaGetSymbolAddress((void**)&pehs, g_ehs);
    cudaGetSymbolAddress((void**)&pip,  g_ip);
    cudaGetSymbolAddress((void**)&pipkS,g_ipkS);
    cudaGetSymbolAddress((void**)&pw,   g_w);
    cudaGetSymbolAddress((void**)&pmm,  g_mm);

    // 1) fold LoRA into effective weights
    fuse_w_kernel<<<(HIDD*HIDD + 255)/256, 256>>>(Wq, q_down, q_up, pWq, HIDD);
    fuse_w_kernel<<<(CDIM*HIDD + 255)/256, 256>>>(Wk, k_down, k_up, pWk, CDIM);
    fuse_w_kernel<<<(CDIM*HIDD + 255)/256, 256>>>(Wv, v_down, v_up, pWv, CDIM);
    fuse_w_kernel<<<(HIDD*HIDD + 255)/256, 256>>>(Wo, o_down, o_up, pWo, HIDD);

    // 2) pack encoder slices
    pack_enc_kernel<<<((NB*TXTN + NB*IPTN)*CDIM + 255)/256, 256>>>(enc, pehs, pip);

    // 3) projections
    sgemm128<<<dim3(HIDD/128, NB*QLEN/128), 256>>>(hs,   pWq,   pq,   nullptr, NB*QLEN, HIDD, HIDD);
    sgemm128<<<dim3(HIDD/128, 3),           256>>>(pehs, pWk,   pkk,  nullptr, NB*TXTN, HIDD, CDIM);
    sgemm128<<<dim3(HIDD/128, 3),           256>>>(pehs, pWv,   pvv,  nullptr, NB*TXTN, HIDD, CDIM);
    sgemm128<<<dim3(HIDD/128, 1),           256>>>(pip,  Wk_ip, pipk, nullptr, NB*IPTN, HIDD, CDIM);
    sgemm128<<<dim3(HIDD/128, 1),           256>>>(pip,  Wv_ip, pipv, nullptr, NB*IPTN, HIDD, CDIM);

    // 4) w = scale * q_full . (sum_t ipk), then per-batch min/max
    ipksum_kernel<<<(NB*HIDD + 255)/256, 256>>>(pipk, pipkS);
    wsum_kernel<<<NB*QLEN/8, 256>>>(pq, pipkS, pw);
    minmax_kernel<<<NB, 256>>>(pw, pmm);

    // 5) fused text + IP attention -> hid
    attn_kernel<<<dim3(QLEN/128, NHEAD, NB), 128>>>(pq, pkk, pvv, pipk, pipv, pw, pmm, phid);

    // 6) output projection (+bias) -> d_out
    sgemm128<<<dim3(HIDD/128, NB*QLEN/128), 256>>>(phid, pWo, out, bo, NB*QLEN, HIDD, HIDD);
}

// round 4
// speedup vs baseline: 1.9300x; 1.9300x over previous
#include <cuda_runtime.h>
#include <cstdint>

#define NB    4
#define QLEN  4096
#define HIDD  1024
#define NHEAD 16
#define HDIM  64
#define TXTN  77
#define IPTN  8
#define CDIM  768
#define ENCR  85   // TXT + IPT

// ---------------- scratch (no allocation allowed) ----------------
__device__ float g_Wq [HIDD*HIDD];
__device__ float g_Wk [CDIM*HIDD];
__device__ float g_Wv [CDIM*HIDD];
__device__ float g_Wo [HIDD*HIDD];
__device__ float g_q  [NB*QLEN*HIDD];
__device__ float g_hid[NB*QLEN*HIDD];
__device__ float g_kk [NB*TXTN*HIDD];
__device__ float g_vv [NB*TXTN*HIDD];
__device__ float g_ipk[NB*IPTN*HIDD];
__device__ float g_ipv[NB*IPTN*HIDD];
__device__ float g_ehs[NB*TXTN*CDIM];
__device__ float g_ip [NB*IPTN*CDIM];
__device__ float g_ipkS[NB*HIDD];
__device__ float g_wqs[NB*HIDD];          // Wq_eff @ ipkSum  (per batch)
__device__ float g_w  [NB*QLEN];
__device__ float g_mm [2*NB];

// ---------------- fold rank-4 LoRA into weight ----------------
__global__ void fuse_w_kernel(const float* __restrict__ W,
                              const float* __restrict__ down,
                              const float* __restrict__ up,
                              float* __restrict__ out, int K)
{
    int idx = blockIdx.x * 256 + threadIdx.x;
    if (idx >= K * HIDD) return;
    int r = idx >> 10, c = idx & 1023;
    float acc = W[idx];
#pragma unroll
    for (int j = 0; j < 4; j++)
        acc = fmaf(down[r*4 + j], up[j*HIDD + c], acc);
    out[idx] = acc;
}

// ---------------- pack encoder slices contiguous ----------------
__global__ void pack_enc_kernel(const float* __restrict__ enc,
                                float* __restrict__ ehs,
                                float* __restrict__ ipb)
{
    int idx = blockIdx.x * 256 + threadIdx.x;
    const int n1 = NB*TXTN*CDIM;
    const int n2 = NB*IPTN*CDIM;
    if (idx < n1) {
        int b = idx / (TXTN*CDIM);
        int rem = idx - b*(TXTN*CDIM);
        int t = rem / CDIM, c = rem - t*CDIM;
        ehs[idx] = enc[((size_t)b*ENCR + t)*CDIM + c];
    } else if (idx < n1 + n2) {
        int k = idx - n1;
        int b = k / (IPTN*CDIM);
        int rem = k - b*(IPTN*CDIM);
        int t = rem / CDIM, c = rem - t*CDIM;
        ipb[k] = enc[((size_t)b*ENCR + TXTN + t)*CDIM + c];
    }
}

// ---------------- small fp32 GEMM (kept for the tiny encoder projections) ----
__global__ __launch_bounds__(256) void sgemm128(
    const float* __restrict__ A, const float* __restrict__ B,
    float* __restrict__ C, const float* __restrict__ bias,
    int M, int N, int K)
{
    __shared__ float As[8][128];
    __shared__ float Bs[8][128];
    const int tid = threadIdx.x;
    const int bx = blockIdx.x, by = blockIdx.y;
    const int tcol = tid & 15, trow = tid >> 4;
    const int a_row = tid >> 1, a_col = (tid & 1) << 2;
    const int b_row = tid >> 5, b_col = (tid & 31) << 2;

    const float* Ab = A + (size_t)by * 128 * K;
    const float* Bb = B + bx * 128;
    const int arow_g = by * 128 + a_row;
    const bool aval = (arow_g < M);

    float acc[8][8];
#pragma unroll
    for (int i = 0; i < 8; i++)
#pragma unroll
        for (int j = 0; j < 8; j++) acc[i][j] = 0.f;

    for (int k0 = 0; k0 < K; k0 += 8) {
        float4 av = aval ? *(const float4*)(Ab + (size_t)a_row*K + k0 + a_col)
                         : make_float4(0.f, 0.f, 0.f, 0.f);
        As[a_col + 0][a_row] = av.x;
        As[a_col + 1][a_row] = av.y;
        As[a_col + 2][a_row] = av.z;
        As[a_col + 3][a_row] = av.w;
        float4 bv = *(const float4*)(Bb + (size_t)(k0 + b_row)*N + b_col);
        *(float4*)&Bs[b_row][b_col] = bv;
        __syncthreads();
#pragma unroll
        for (int kk = 0; kk < 8; kk++) {
            float ra[8], rb[8];
            *(float4*)(ra)     = *(const float4*)&As[kk][trow*8];
            *(float4*)(ra + 4) = *(const float4*)&As[kk][trow*8 + 4];
            *(float4*)(rb)     = *(const float4*)&Bs[kk][tcol*8];
            *(float4*)(rb + 4) = *(const float4*)&Bs[kk][tcol*8 + 4];
#pragma unroll
            for (int i = 0; i < 8; i++)
#pragma unroll
                for (int j = 0; j < 8; j++)
                    acc[i][j] = fmaf(ra[i], rb[j], acc[i][j]);
        }
        __syncthreads();
    }

    const int rb0 = by*128 + trow*8;
    const int cb0 = bx*128 + tcol*8;
#pragma unroll
    for (int i = 0; i < 8; i++) {
        int r = rb0 + i;
        if (r >= M) continue;
#pragma unroll
        for (int j = 0; j < 8; j += 4) {
            float4 v = make_float4(acc[i][j], acc[i][j+1], acc[i][j+2], acc[i][j+3]);
            if (bias) {
                v.x += bias[cb0 + j + 0];
                v.y += bias[cb0 + j + 1];
                v.z += bias[cb0 + j + 2];
                v.w += bias[cb0 + j + 3];
            }
            *(float4*)(C + (size_t)r*N + cb0 + j) = v;
        }
    }
}

// ================= TF32 tensor-core GEMM: C[M,N] = A[M,K] @ B[K,N] (+bias) ====
// CTA tile 128x128, BK=16, 4 warps (64x64 each), cp.async double buffer.
// Requires: M%128==0, N%128==0, K%16==0.
#define APAD 20    // As row stride (floats): conflict-free A-fragment loads
#define BPAD 136   // Bs row stride (floats): conflict-free B-fragment loads

__device__ __forceinline__ uint32_t f2tf(float x) {
    uint32_t r;
    asm("cvt.rna.tf32.f32 %0, %1;" : "=r"(r) : "f"(x));
    return r;
}
__device__ __forceinline__ void mma_tf32(float* c, const uint32_t* a, const uint32_t* b) {
    asm volatile("mma.sync.aligned.m16n8k8.row.col.f32.tf32.tf32.f32 "
        "{%0,%1,%2,%3}, {%4,%5,%6,%7}, {%8,%9}, {%0,%1,%2,%3};"
        : "+f"(c[0]), "+f"(c[1]), "+f"(c[2]), "+f"(c[3])
        : "r"(a[0]), "r"(a[1]), "r"(a[2]), "r"(a[3]), "r"(b[0]), "r"(b[1]));
}
__device__ __forceinline__ void cp16(uint32_t s, const void* g) {
    asm volatile("cp.async.ca.shared.global [%0], [%1], 16;" :: "r"(s), "l"(g));
}
__device__ __forceinline__ void cp_commit() {
    asm volatile("cp.async.commit_group;");
}
template<int N_> __device__ __forceinline__ void cp_wait() {
    asm volatile("cp.async.wait_group %0;" :: "n"(N_));
}

__global__ __launch_bounds__(128) void gemm_tf32(
    const float* __restrict__ A, const float* __restrict__ B,
    float* __restrict__ C, const float* __restrict__ bias,
    int M, int N, int K)
{
    __shared__ float As[2][128*APAD];
    __shared__ float Bs[2][16*BPAD];

    const int tid  = threadIdx.x;
    const int lane = tid & 31;
    const int warp = tid >> 5;
    const int wm = (warp >> 1) * 64;
    const int wn = (warp & 1) * 64;
    const int bx = blockIdx.x, by = blockIdx.y;

    const float* Ag = A + (size_t)by * 128 * K;
    const float* Bg = B + bx * 128;

    // staging maps (4 float4 per thread for each of A, B)
    const int a_colv = tid & 3;          // float4 col in [0,4)
    const int a_rowb = tid >> 2;         // base row, +32*i
    const int b_colv = tid & 31;         // float4 col in [0,32)
    const int b_rowb = tid >> 5;         // base row, +4*i

    const uint32_t as0 = (uint32_t)__cvta_generic_to_shared(&As[0][0]);
    const uint32_t bs0 = (uint32_t)__cvta_generic_to_shared(&Bs[0][0]);

    float acc[4][8][4];
#pragma unroll
    for (int i = 0; i < 4; i++)
#pragma unroll
        for (int j = 0; j < 8; j++)
#pragma unroll
            for (int r = 0; r < 4; r++) acc[i][j][r] = 0.f;

    auto load_stage = [&](int k0, int buf) {
        uint32_t asb = as0 + (uint32_t)buf * (128*APAD*4);
        uint32_t bsb = bs0 + (uint32_t)buf * (16*BPAD*4);
#pragma unroll
        for (int i = 0; i < 4; i++) {
            int row = a_rowb + i*32;
            cp16(asb + (uint32_t)(row*APAD + a_colv*4)*4,
                 Ag + (size_t)row*K + k0 + a_colv*4);
        }
#pragma unroll
        for (int i = 0; i < 4; i++) {
            int row = b_rowb + i*4;
            cp16(bsb + (uint32_t)(row*BPAD + b_colv*4)*4,
                 Bg + (size_t)(k0 + row)*N + b_colv*4);
        }
    };

    const int nstage = K / 16;
    load_stage(0, 0);
    cp_commit();

    int buf = 0;
    for (int s = 0; s < nstage; s++) {
        if (s + 1 < nstage) {
            load_stage((s + 1)*16, buf ^ 1);
            cp_commit();
            cp_wait<1>();
        } else {
            cp_wait<0>();
        }
        __syncthreads();

        const float* as = As[buf];
        const float* bs = Bs[buf];
#pragma unroll
        for (int ks = 0; ks < 16; ks += 8) {
            uint32_t af[4][4];
#pragma unroll
            for (int im = 0; im < 4; im++) {
                const float* ap = as + (wm + im*16 + (lane >> 2))*APAD + ks + (lane & 3);
                af[im][0] = f2tf(ap[0]);
                af[im][1] = f2tf(ap[8*APAD]);
                af[im][2] = f2tf(ap[4]);
                af[im][3] = f2tf(ap[8*APAD + 4]);
            }
            uint32_t bf[8][2];
#pragma unroll
            for (int jn = 0; jn < 8; jn++) {
                const float* bp = bs + (ks + (lane & 3))*BPAD + wn + jn*8 + (lane >> 2);
                bf[jn][0] = f2tf(bp[0]);
                bf[jn][1] = f2tf(bp[4*BPAD]);
            }
#pragma unroll
            for (int im = 0; im < 4; im++)
#pragma unroll
                for (int jn = 0; jn < 8; jn++)
                    mma_tf32(acc[im][jn], af[im], bf[jn]);
        }
        __syncthreads();
        buf ^= 1;
    }

    // epilogue
#pragma unroll
    for (int im = 0; im < 4; im++) {
#pragma unroll
        for (int jn = 0; jn < 8; jn++) {
            int r = by*128 + wm + im*16 + (lane >> 2);
            int c = bx*128 + wn + jn*8 + 2*(lane & 3);
            float2 v0 = make_float2(acc[im][jn][0], acc[im][jn][1]);
            float2 v1 = make_float2(acc[im][jn][2], acc[im][jn][3]);
            if (bias) {
                float2 bv = *(const float2*)(bias + c);
                v0.x += bv.x; v0.y += bv.y;
                v1.x += bv.x; v1.y += bv.y;
            }
            *(float2*)(C + (size_t)r*N + c)       = v0;
            *(float2*)(C + (size_t)(r + 8)*N + c) = v1;
        }
    }
}

// ---------------- ipk token-sum: [B,8,1024] -> [B,1024] ----------------
__global__ void ipksum_kernel(const float* __restrict__ ipk, float* __restrict__ out)
{
    int idx = blockIdx.x * 256 + threadIdx.x;
    if (idx >= NB * HIDD) return;
    int b = idx >> 10, j = idx & 1023;
    float s = 0.f;
#pragma unroll
    for (int t = 0; t < IPTN; t++)
        s += ipk[((size_t)b*IPTN + t)*HIDD + j];
    out[idx] = s;
}

// ---------------- v[b] = Wq_eff @ ipkSum[b]  (fp32-exact gate path) ----------
__global__ __launch_bounds__(256) void wqs_matvec_kernel(
    const float* __restrict__ W,     // [1024,1024] row = input dim i, col = out j
    const float* __restrict__ s,     // [B,1024]
    float* __restrict__ v)           // [B,1024]  v[i] = sum_j W[i][j]*s[j]
{
    __shared__ float sv[HIDD];
    const int b = blockIdx.y;
    for (int i = threadIdx.x; i < HIDD; i += 256) sv[i] = s[b*HIDD + i];
    __syncthreads();
    const int warp = threadIdx.x >> 5, lane = threadIdx.x & 31;
    const int row = blockIdx.x * 8 + warp;
    const float* wr = W + (size_t)row * HIDD;
    float acc = 0.f;
#pragma unroll
    for (int i = 0; i < 32; i++)
        acc = fmaf(wr[lane + 32*i], sv[lane + 32*i], acc);
#pragma unroll
    for (int off = 16; off > 0; off >>= 1)
        acc += __shfl_xor_sync(0xffffffffu, acc, off);
    if (lane == 0) v[b*HIDD + row] = acc;
}

// ---------------- w[b,q] = scale * dot(hs_row, v_b)  (fp32-exact) ------------
__global__ __launch_bounds__(256) void wsum_kernel(const float* __restrict__ hs,
                                                   const float* __restrict__ vb,
                                                   float* __restrict__ w)
{
    __shared__ float sk[HIDD];
    const int row0 = blockIdx.x * 8;          // 8 rows/block, same batch
    const int b = row0 / QLEN;
    for (int i = threadIdx.x; i < HIDD; i += 256) sk[i] = vb[b*HIDD + i];
    __syncthreads();
    const int warp = threadIdx.x >> 5, lane = threadIdx.x & 31;
    const int row = row0 + warp;
    const float* qr = hs + (size_t)row * HIDD;
    float s = 0.f;
#pragma unroll
    for (int i = 0; i < 32; i++)
        s = fmaf(qr[lane + 32*i], sk[lane + 32*i], s);
#pragma unroll
    for (int off = 16; off > 0; off >>= 1)
        s += __shfl_xor_sync(0xffffffffu, s, off);
    if (lane == 0) w[row] = 0.125f * s;
}

// ---------------- per-batch min/max of w ----------------
__global__ void minmax_kernel(const float* __restrict__ w, float* __restrict__ mm)
{
    __shared__ float smn[256], smx[256];
    const int b = blockIdx.x, tid = threadIdx.x;
    float mn = 1e30f, mx = -1e30f;
    for (int i = tid; i < QLEN; i += 256) {
        float v = w[b*QLEN + i];
        mn = fminf(mn, v); mx = fmaxf(mx, v);
    }
    smn[tid] = mn; smx[tid] = mx;
    __syncthreads();
    for (int s = 128; s > 0; s >>= 1) {
        if (tid < s) {
            smn[tid] = fminf(smn[tid], smn[tid + s]);
            smx[tid] = fmaxf(smx[tid], smx[tid + s]);
        }
        __syncthreads();
    }
    if (tid == 0) { mm[2*b] = smn[0]; mm[2*b + 1] = smx[0]; }
}

// ---------------- fused attention: text softmax-attn + IP attn + aw combine --
__global__ __launch_bounds__(128) void attn_kernel(
    const float* __restrict__ qb,   // [B,Q,1024]
    const float* __restrict__ kk,   // [B,77,1024]
    const float* __restrict__ vv,
    const float* __restrict__ ipk,  // [B,8,1024]
    const float* __restrict__ ipv,
    const float* __restrict__ wbuf, // [B,Q]
    const float* __restrict__ mm,   // [B][min,max]
    float* __restrict__ hid)        // [B,Q,1024]
{
    __shared__ float smem[TXTN*HDIM*2 + IPTN*HDIM*2];   // 10880 floats = 43520 B
    float* sK  = smem;
    float* sV  = smem + TXTN*HDIM;
    float* sIK = smem + 2*TXTN*HDIM;
    float* sIV = sIK + IPTN*HDIM;

    const int tid = threadIdx.x;
    const int b = blockIdx.z, h = blockIdx.y, q0 = blockIdx.x * 128;

    const size_t kvbase = ((size_t)b*TXTN)*HIDD + h*HDIM;
    for (int i = tid; i < TXTN*HDIM; i += 128) {
        int t = i >> 6, d = i & 63;
        sK[i] = kk[kvbase + (size_t)t*HIDD + d];
        sV[i] = vv[kvbase + (size_t)t*HIDD + d];
    }
    const size_t ipbase = ((size_t)b*IPTN)*HIDD + h*HDIM;
    for (int i = tid; i < IPTN*HDIM; i += 128) {
        int t = i >> 6, d = i & 63;
        sIK[i] = ipk[ipbase + (size_t)t*HIDD + d];
        sIV[i] = ipv[ipbase + (size_t)t*HIDD + d];
    }
    __syncthreads();

    const int qi = q0 + tid;
    float4 q4[16];
    const float4* qp = (const float4*)(qb + ((size_t)b*QLEN + qi)*HIDD + h*HDIM);
#pragma unroll
    for (int i = 0; i < 16; i++) q4[i] = qp[i];

    float m = -1e30f, l = 0.f;
    float4 o4[16];
#pragma unroll
    for (int i = 0; i < 16; i++) o4[i] = make_float4(0.f, 0.f, 0.f, 0.f);

    for (int t = 0; t < TXTN; t++) {
        const float4* kp = (const float4*)(sK + t*HDIM);
        float s = 0.f;
#pragma unroll
        for (int i = 0; i < 16; i++) {
            float4 kv = kp[i];
            s = fmaf(q4[i].x, kv.x, s); s = fmaf(q4[i].y, kv.y, s);
            s = fmaf(q4[i].z, kv.z, s); s = fmaf(q4[i].w, kv.w, s);
        }
        s *= 0.125f;
        if (s > m) {
            float c = __expf(m - s);
            l *= c;
#pragma unroll
            for (int i = 0; i < 16; i++) {
                o4[i].x *= c; o4[i].y *= c; o4[i].z *= c; o4[i].w *= c;
            }
            m = s;
        }
        float p = __expf(s - m);
        l += p;
        const float4* vp = (const float4*)(sV + t*HDIM);
#pragma unroll
        for (int i = 0; i < 16; i++) {
            float4 v = vp[i];
            o4[i].x = fmaf(p, v.x, o4[i].x); o4[i].y = fmaf(p, v.y, o4[i].y);
            o4[i].z = fmaf(p, v.z, o4[i].z); o4[i].w = fmaf(p, v.w, o4[i].w);
        }
    }
    const float inv_l = 1.f / l;

    float sip[IPTN];
#pragma unroll
    for (int t = 0; t < IPTN; t++) {
        const float4* kp = (const float4*)(sIK + t*HDIM);
        float s = 0.f;
#pragma unroll
        for (int i = 0; i < 16; i++) {
            float4 kv = kp[i];
            s = fmaf(q4[i].x, kv.x, s); s = fmaf(q4[i].y, kv.y, s);
            s = fmaf(q4[i].z, kv.z, s); s = fmaf(q4[i].w, kv.w, s);
        }
        sip[t] = s * 0.125f;
    }
    const int gr = qi >> 6, gc = qi & 63;
    const int region = (gr < 32) ? ((gc < 32) ? 0 : -1)
                                 : ((gc >= 32) ? 1 : -1);
    if (region == 0) { sip[4] = sip[5] = sip[6] = sip[7] = -1e30f; }
    else if (region == 1) { sip[0] = sip[1] = sip[2] = sip[3] = -1e30f; }

    float m2 = -1e30f;
#pragma unroll
    for (int t = 0; t < IPTN; t++) m2 = fmaxf(m2, sip[t]);
    float p2[IPTN], sum2 = 0.f;
#pragma unroll
    for (int t = 0; t < IPTN; t++) { p2[t] = __expf(sip[t] - m2); sum2 += p2[t]; }

    const float wv  = wbuf[b*QLEN + qi];
    const float wmn = mm[2*b], wmx = mm[2*b + 1];
    float aw = (wv - wmn) / (wmx - wmn);
    aw = (aw < 0.3f) ? 0.f : aw;
    aw *= 0.5f;
    if (region >= 0) aw = aw * 2.f + 1.f;
    const float coeff = aw / sum2;

#pragma unroll
    for (int i = 0; i < 16; i++) {
        float4 acc = make_float4(0.f, 0.f, 0.f, 0.f);
#pragma unroll
        for (int t = 0; t < IPTN; t++) {
            float4 v = ((const float4*)(sIV + t*HDIM))[i];
            acc.x = fmaf(p2[t], v.x, acc.x); acc.y = fmaf(p2[t], v.y, acc.y);
            acc.z = fmaf(p2[t], v.z, acc.z); acc.w = fmaf(p2[t], v.w, acc.w);
        }
        o4[i].x = o4[i].x * inv_l + coeff * acc.x;
        o4[i].y = o4[i].y * inv_l + coeff * acc.y;
        o4[i].z = o4[i].z * inv_l + coeff * acc.z;
        o4[i].w = o4[i].w * inv_l + coeff * acc.w;
    }

    __syncthreads();
    float* so = smem;
#pragma unroll
    for (int i = 0; i < 16; i++)
        *(float4*)(so + tid*68 + i*4) = o4[i];
    __syncthreads();

    float* outp = hid + ((size_t)b*QLEN + q0)*HIDD + h*HDIM;
    for (int i4 = tid; i4 < 128*16; i4 += 128) {
        int r = i4 >> 4, c = i4 & 15;
        float4 v = *(const float4*)(so + r*68 + c*4);
        *(float4*)(outp + (size_t)r*HIDD + c*4) = v;
    }
}

// ---------------- host launcher ----------------
extern "C" void kernel_launch(void* const* d_in, const int* in_sizes, int n_in,
                              void* d_out, int out_size)
{
    const float* hs     = (const float*)d_in[0];
    const float* enc    = (const float*)d_in[1];
    const float* Wq     = (const float*)d_in[2];
    const float* Wk     = (const float*)d_in[3];
    const float* Wv     = (const float*)d_in[4];
    const float* Wo     = (const float*)d_in[5];
    const float* bo     = (const float*)d_in[6];
    const float* q_down = (const float*)d_in[7];
    const float* q_up   = (const float*)d_in[8];
    const float* k_down = (const float*)d_in[9];
    const float* k_up   = (const float*)d_in[10];
    const float* v_down = (const float*)d_in[11];
    const float* v_up   = (const float*)d_in[12];
    const float* o_down = (const float*)d_in[13];
    const float* o_up   = (const float*)d_in[14];
    const float* Wk_ip  = (const float*)d_in[15];
    const float* Wv_ip  = (const float*)d_in[16];
    float* out = (float*)d_out;

    float *pWq, *pWk, *pWv, *pWo, *pq, *phid, *pkk, *pvv, *pipk, *pipv;
    float *pehs, *pip, *pipkS, *pwqs, *pw, *pmm;
    cudaGetSymbolAddress((void**)&pWq,  g_Wq);
    cudaGetSymbolAddress((void**)&pWk,  g_Wk);
    cudaGetSymbolAddress((void**)&pWv,  g_Wv);
    cudaGetSymbolAddress((void**)&pWo,  g_Wo);
    cudaGetSymbolAddress((void**)&pq,   g_q);
    cudaGetSymbolAddress((void**)&phid, g_hid);
    cudaGetSymbolAddress((void**)&pkk,  g_kk);
    cudaGetSymbolAddress((void**)&pvv,  g_vv);
    cudaGetSymbolAddress((void**)&pipk, g_ipk);
    cudaGetSymbolAddress((void**)&pipv, g_ipv);
    cudaGetSymbolAddress((void**)&pehs, g_ehs);
    cudaGetSymbolAddress((void**)&pip,  g_ip);
    cudaGetSymbolAddress((void**)&pipkS,g_ipkS);
    cudaGetSymbolAddress((void**)&pwqs, g_wqs);
    cudaGetSymbolAddress((void**)&pw,   g_w);
    cudaGetSymbolAddress((void**)&pmm,  g_mm);

    // 1) fold LoRA into effective weights
    fuse_w_kernel<<<(HIDD*HIDD + 255)/256, 256>>>(Wq, q_down, q_up, pWq, HIDD);
    fuse_w_kernel<<<(CDIM*HIDD + 255)/256, 256>>>(Wk, k_down, k_up, pWk, CDIM);
    fuse_w_kernel<<<(CDIM*HIDD + 255)/256, 256>>>(Wv, v_down, v_up, pWv, CDIM);
    fuse_w_kernel<<<(HIDD*HIDD + 255)/256, 256>>>(Wo, o_down, o_up, pWo, HIDD);

    // 2) pack encoder slices
    pack_enc_kernel<<<((NB*TXTN + NB*IPTN)*CDIM + 255)/256, 256>>>(enc, pehs, pip);

    // 3) projections: big ones on tensor cores (TF32), small ones fp32
    gemm_tf32<<<dim3(HIDD/128, NB*QLEN/128), 128>>>(hs, pWq, pq, nullptr, NB*QLEN, HIDD, HIDD);
    sgemm128<<<dim3(HIDD/128, 3), 256>>>(pehs, pWk,   pkk,  nullptr, NB*TXTN, HIDD, CDIM);
    sgemm128<<<dim3(HIDD/128, 3), 256>>>(pehs, pWv,   pvv,  nullptr, NB*TXTN, HIDD, CDIM);
    sgemm128<<<dim3(HIDD/128, 1), 256>>>(pip,  Wk_ip, pipk, nullptr, NB*IPTN, HIDD, CDIM);
    sgemm128<<<dim3(HIDD/128, 1), 256>>>(pip,  Wv_ip, pipv, nullptr, NB*IPTN, HIDD, CDIM);

    // 4) exact fp32 gate: w = scale * hs . (Wq_eff @ sum_t ipk)
    ipksum_kernel<<<(NB*HIDD + 255)/256, 256>>>(pipk, pipkS);
    wqs_matvec_kernel<<<dim3(HIDD/8, NB), 256>>>(pWq, pipkS, pwqs);
    wsum_kernel<<<NB*QLEN/8, 256>>>(hs, pwqs, pw);
    minmax_kernel<<<NB, 256>>>(pw, pmm);

    // 5) fused text + IP attention -> hid
    attn_kernel<<<dim3(QLEN/128, NHEAD, NB), 128>>>(pq, pkk, pvv, pipk, pipv, pw, pmm, phid);

    // 6) output projection (+bias) -> d_out, TF32 tensor cores
    gemm_tf32<<<dim3(HIDD/128, NB*QLEN/128), 128>>>(phid, pWo, out, bo, NB*QLEN, HIDD, HIDD);
}

// round 5
// speedup vs baseline: 2.8414x; 1.4722x over previous
#include <cuda_runtime.h>
#include <cstdint>

#define NB    4
#define QLEN  4096
#define HIDD  1024
#define NHEAD 16
#define HDIM  64
#define TXTN  77
#define IPTN  8
#define CDIM  768
#define ENCR  85   // TXT + IPT

// ---------------- scratch (no allocation allowed) ----------------
__device__ float g_Wq  [HIDD*HIDD];   // fp32-exact (gate path)
__device__ float g_WqR [HIDD*HIDD];   // tf32-rounded (GEMM path)
__device__ float g_WkR [CDIM*HIDD];
__device__ float g_WvR [CDIM*HIDD];
__device__ float g_WoR [HIDD*HIDD];
__device__ float g_q   [NB*QLEN*HIDD];
__device__ float g_hid [NB*QLEN*HIDD];   // stored pre-rounded to tf32
__device__ float g_kk  [NB*TXTN*HIDD];
__device__ float g_vv  [NB*TXTN*HIDD];
__device__ float g_ipk [NB*IPTN*HIDD];
__device__ float g_ipv [NB*IPTN*HIDD];
__device__ float g_ehs [NB*TXTN*CDIM];
__device__ float g_ip  [NB*IPTN*CDIM];
__device__ float g_ipsum[NB*CDIM];
__device__ float g_ipkS[NB*HIDD];
__device__ float g_wqs [NB*HIDD];
__device__ float g_w   [NB*QLEN];
__device__ float g_mm  [2*NB];

__device__ __forceinline__ uint32_t f2tf(float x) {
    uint32_t r;
    asm("cvt.rna.tf32.f32 %0, %1;" : "=r"(r) : "f"(x));
    return r;
}
__device__ __forceinline__ float roundtf(float x) {
    return __uint_as_float(f2tf(x));
}

// ---------------- fold rank-4 LoRA into weight (fp32 and/or tf32-rounded) ----
__global__ void fuse_w_kernel(const float* __restrict__ W,
                              const float* __restrict__ down,
                              const float* __restrict__ up,
                              float* __restrict__ outF,
                              float* __restrict__ outR, int K)
{
    int idx = blockIdx.x * 256 + threadIdx.x;
    if (idx >= K * HIDD) return;
    int r = idx >> 10, c = idx & 1023;
    float acc = W[idx];
#pragma unroll
    for (int j = 0; j < 4; j++)
        acc = fmaf(down[r*4 + j], up[j*HIDD + c], acc);
    if (outF) outF[idx] = acc;
    outR[idx] = roundtf(acc);
}

// ---------------- pack encoder slices contiguous ----------------
__global__ void pack_enc_kernel(const float* __restrict__ enc,
                                float* __restrict__ ehs,
                                float* __restrict__ ipb)
{
    int idx = blockIdx.x * 256 + threadIdx.x;
    const int n1 = NB*TXTN*CDIM;
    const int n2 = NB*IPTN*CDIM;
    if (idx < n1) {
        int b = idx / (TXTN*CDIM);
        int rem = idx - b*(TXTN*CDIM);
        int t = rem / CDIM, c = rem - t*CDIM;
        ehs[idx] = enc[((size_t)b*ENCR + t)*CDIM + c];
    } else if (idx < n1 + n2) {
        int k = idx - n1;
        int b = k / (IPTN*CDIM);
        int rem = k - b*(IPTN*CDIM);
        int t = rem / CDIM, c = rem - t*CDIM;
        ipb[k] = enc[((size_t)b*ENCR + TXTN + t)*CDIM + c];
    }
}

// ================= TF32 tensor-core GEMM: C[M,N] = A[M,K] @ B[K,N] (+bias) ====
// CTA tile 128x128, BK=16, 4 warps (64x64 each), cp.async double buffer.
// N%128==0, K%16==0; M arbitrary (row-clamped loads + guarded epilogue).
// CVTA/CVTB: round operand to tf32 in-kernel; false = operand pre-rounded.
#define APAD 20
#define BPAD 136

__device__ __forceinline__ void mma_tf32(float* c, const uint32_t* a, const uint32_t* b) {
    asm volatile("mma.sync.aligned.m16n8k8.row.col.f32.tf32.tf32.f32 "
        "{%0,%1,%2,%3}, {%4,%5,%6,%7}, {%8,%9}, {%0,%1,%2,%3};"
        : "+f"(c[0]), "+f"(c[1]), "+f"(c[2]), "+f"(c[3])
        : "r"(a[0]), "r"(a[1]), "r"(a[2]), "r"(a[3]), "r"(b[0]), "r"(b[1]));
}
__device__ __forceinline__ void cp16(uint32_t s, const void* g) {
    asm volatile("cp.async.ca.shared.global [%0], [%1], 16;" :: "r"(s), "l"(g));
}
__device__ __forceinline__ void cp_commit() {
    asm volatile("cp.async.commit_group;");
}
template<int N_> __device__ __forceinline__ void cp_wait() {
    asm volatile("cp.async.wait_group %0;" :: "n"(N_));
}
template<bool CVT>
__device__ __forceinline__ uint32_t ldfrag(const float* p) {
    float v = *p;
    return CVT ? f2tf(v) : __float_as_uint(v);
}

template<bool CVTA, bool CVTB>
__global__ __launch_bounds__(128) void gemm_tf32(
    const float* __restrict__ A, const float* __restrict__ B,
    float* __restrict__ C, const float* __restrict__ bias,
    int M, int N, int K)
{
    __shared__ float As[2][128*APAD];
    __shared__ float Bs[2][16*BPAD];

    const int tid  = threadIdx.x;
    const int lane = tid & 31;
    const int warp = tid >> 5;
    const int wm = (warp >> 1) * 64;
    const int wn = (warp & 1) * 64;
    const int bx = blockIdx.x, by = blockIdx.y;

    const float* Bg = B + bx * 128;

    const int a_colv = tid & 3;
    const int a_rowb = tid >> 2;
    const int b_colv = tid & 31;
    const int b_rowb = tid >> 5;

    const uint32_t as0 = (uint32_t)__cvta_generic_to_shared(&As[0][0]);
    const uint32_t bs0 = (uint32_t)__cvta_generic_to_shared(&Bs[0][0]);

    float acc[4][8][4];
#pragma unroll
    for (int i = 0; i < 4; i++)
#pragma unroll
        for (int j = 0; j < 8; j++)
#pragma unroll
            for (int r = 0; r < 4; r++) acc[i][j][r] = 0.f;

    auto load_stage = [&](int k0, int buf) {
        uint32_t asb = as0 + (uint32_t)buf * (128*APAD*4);
        uint32_t bsb = bs0 + (uint32_t)buf * (16*BPAD*4);
#pragma unroll
        for (int i = 0; i < 4; i++) {
            int row = a_rowb + i*32;
            int rg = by*128 + row; if (rg > M-1) rg = M-1;   // row-clamped (garbage discarded)
            cp16(asb + (uint32_t)(row*APAD + a_colv*4)*4,
                 A + (size_t)rg*K + k0 + a_colv*4);
        }
#pragma unroll
        for (int i = 0; i < 4; i++) {
            int row = b_rowb + i*4;
            cp16(bsb + (uint32_t)(row*BPAD + b_colv*4)*4,
                 Bg + (size_t)(k0 + row)*N + b_colv*4);
        }
    };

    const int nstage = K / 16;
    load_stage(0, 0);
    cp_commit();

    int buf = 0;
    for (int s = 0; s < nstage; s++) {
        if (s + 1 < nstage) {
            load_stage((s + 1)*16, buf ^ 1);
            cp_commit();
            cp_wait<1>();
        } else {
            cp_wait<0>();
        }
        __syncthreads();

        const float* as = As[buf];
        const float* bs = Bs[buf];
#pragma unroll
        for (int ks = 0; ks < 16; ks += 8) {
            uint32_t af[4][4];
#pragma unroll
            for (int im = 0; im < 4; im++) {
                const float* ap = as + (wm + im*16 + (lane >> 2))*APAD + ks + (lane & 3);
                af[im][0] = ldfrag<CVTA>(ap);
                af[im][1] = ldfrag<CVTA>(ap + 8*APAD);
                af[im][2] = ldfrag<CVTA>(ap + 4);
                af[im][3] = ldfrag<CVTA>(ap + 8*APAD + 4);
            }
            uint32_t bf[8][2];
#pragma unroll
            for (int jn = 0; jn < 8; jn++) {
                const float* bp = bs + (ks + (lane & 3))*BPAD + wn + jn*8 + (lane >> 2);
                bf[jn][0] = ldfrag<CVTB>(bp);
                bf[jn][1] = ldfrag<CVTB>(bp + 4*BPAD);
            }
#pragma unroll
            for (int im = 0; im < 4; im++)
#pragma unroll
                for (int jn = 0; jn < 8; jn++)
                    mma_tf32(acc[im][jn], af[im], bf[jn]);
        }
        __syncthreads();
        buf ^= 1;
    }

#pragma unroll
    for (int im = 0; im < 4; im++) {
#pragma unroll
        for (int jn = 0; jn < 8; jn++) {
            int r = by*128 + wm + im*16 + (lane >> 2);
            int c = bx*128 + wn + jn*8 + 2*(lane & 3);
            float2 v0 = make_float2(acc[im][jn][0], acc[im][jn][1]);
            float2 v1 = make_float2(acc[im][jn][2], acc[im][jn][3]);
            if (bias) {
                float2 bv = *(const float2*)(bias + c);
                v0.x += bv.x; v0.y += bv.y;
                v1.x += bv.x; v1.y += bv.y;
            }
            if (r < M)     *(float2*)(C + (size_t)r*N + c)       = v0;
            if (r + 8 < M) *(float2*)(C + (size_t)(r + 8)*N + c) = v1;
        }
    }
}

// ---------------- exact fp32 gate path ----------------
// ip token-sum over CDIM: [B,8,768] -> [B,768]
__global__ void ipsum_kernel(const float* __restrict__ ip, float* __restrict__ out)
{
    int idx = blockIdx.x * 256 + threadIdx.x;
    if (idx >= NB * CDIM) return;
    int b = idx / CDIM, c = idx - b*CDIM;
    float s = 0.f;
#pragma unroll
    for (int t = 0; t < IPTN; t++)
        s += ip[((size_t)b*IPTN + t)*CDIM + c];
    out[idx] = s;
}

// ipkS[b,j] = sum_i ipsum[b,i] * Wk_ip[i,j]   (column access, coalesced in j)
__global__ __launch_bounds__(256) void colvec_kernel(
    const float* __restrict__ s, const float* __restrict__ W,
    float* __restrict__ out)
{
    __shared__ float ss[CDIM];
    const int b = blockIdx.y;
    const int j = blockIdx.x * 256 + threadIdx.x;
    for (int i = threadIdx.x; i < CDIM; i += 256) ss[i] = s[b*CDIM + i];
    __syncthreads();
    float acc = 0.f;
#pragma unroll 8
    for (int i = 0; i < CDIM; i++)
        acc = fmaf(ss[i], W[(size_t)i*HIDD + j], acc);
    out[b*HIDD + j] = acc;
}

// v[b,i] = sum_j Wq_fp32[i,j] * ipkS[b,j]
__global__ __launch_bounds__(256) void wqs_matvec_kernel(
    const float* __restrict__ W, const float* __restrict__ s,
    float* __restrict__ v)
{
    __shared__ float sv[HIDD];
    const int b = blockIdx.y;
    for (int i = threadIdx.x; i < HIDD; i += 256) sv[i] = s[b*HIDD + i];
    __syncthreads();
    const int warp = threadIdx.x >> 5, lane = threadIdx.x & 31;
    const int row = blockIdx.x * 8 + warp;
    const float* wr = W + (size_t)row * HIDD;
    float acc = 0.f;
#pragma unroll
    for (int i = 0; i < 32; i++)
        acc = fmaf(wr[lane + 32*i], sv[lane + 32*i], acc);
#pragma unroll
    for (int off = 16; off > 0; off >>= 1)
        acc += __shfl_xor_sync(0xffffffffu, acc, off);
    if (lane == 0) v[b*HIDD + row] = acc;
}

// w[b,q] = 0.125 * dot(hs_row, v_b)
__global__ __launch_bounds__(256) void wsum_kernel(const float* __restrict__ hs,
                                                   const float* __restrict__ vb,
                                                   float* __restrict__ w)
{
    __shared__ float sk[HIDD];
    const int row0 = blockIdx.x * 8;
    const int b = row0 / QLEN;
    for (int i = threadIdx.x; i < HIDD; i += 256) sk[i] = vb[b*HIDD + i];
    __syncthreads();
    const int warp = threadIdx.x >> 5, lane = threadIdx.x & 31;
    const int row = row0 + warp;
    const float* qr = hs + (size_t)row * HIDD;
    float s = 0.f;
#pragma unroll
    for (int i = 0; i < 32; i++)
        s = fmaf(qr[lane + 32*i], sk[lane + 32*i], s);
#pragma unroll
    for (int off = 16; off > 0; off >>= 1)
        s += __shfl_xor_sync(0xffffffffu, s, off);
    if (lane == 0) w[row] = 0.125f * s;
}

// ---------------- per-batch min/max of w ----------------
__global__ void minmax_kernel(const float* __restrict__ w, float* __restrict__ mm)
{
    __shared__ float smn[256], smx[256];
    const int b = blockIdx.x, tid = threadIdx.x;
    float mn = 1e30f, mx = -1e30f;
    for (int i = tid; i < QLEN; i += 256) {
        float v = w[b*QLEN + i];
        mn = fminf(mn, v); mx = fmaxf(mx, v);
    }
    smn[tid] = mn; smx[tid] = mx;
    __syncthreads();
    for (int s = 128; s > 0; s >>= 1) {
        if (tid < s) {
            smn[tid] = fminf(smn[tid], smn[tid + s]);
            smx[tid] = fmaxf(smx[tid], smx[tid + s]);
        }
        __syncthreads();
    }
    if (tid == 0) { mm[2*b] = smn[0]; mm[2*b + 1] = smx[0]; }
}

// ---------------- fused attention: text softmax-attn + IP attn + aw combine --
__global__ __launch_bounds__(128) void attn_kernel(
    const float* __restrict__ qb,
    const float* __restrict__ kk,
    const float* __restrict__ vv,
    const float* __restrict__ ipk,
    const float* __restrict__ ipv,
    const float* __restrict__ wbuf,
    const float* __restrict__ mm,
    float* __restrict__ hid)
{
    __shared__ float smem[TXTN*HDIM*2 + IPTN*HDIM*2];
    float* sK  = smem;
    float* sV  = smem + TXTN*HDIM;
    float* sIK = smem + 2*TXTN*HDIM;
    float* sIV = sIK + IPTN*HDIM;

    const int tid = threadIdx.x;
    const int b = blockIdx.z, h = blockIdx.y, q0 = blockIdx.x * 128;

    const size_t kvbase = ((size_t)b*TXTN)*HIDD + h*HDIM;
    for (int i = tid; i < TXTN*HDIM; i += 128) {
        int t = i >> 6, d = i & 63;
        sK[i] = kk[kvbase + (size_t)t*HIDD + d];
        sV[i] = vv[kvbase + (size_t)t*HIDD + d];
    }
    const size_t ipbase = ((size_t)b*IPTN)*HIDD + h*HDIM;
    for (int i = tid; i < IPTN*HDIM; i += 128) {
        int t = i >> 6, d = i & 63;
        sIK[i] = ipk[ipbase + (size_t)t*HIDD + d];
        sIV[i] = ipv[ipbase + (size_t)t*HIDD + d];
    }
    __syncthreads();

    const int qi = q0 + tid;
    float4 q4[16];
    const float4* qp = (const float4*)(qb + ((size_t)b*QLEN + qi)*HIDD + h*HDIM);
#pragma unroll
    for (int i = 0; i < 16; i++) q4[i] = qp[i];

    float m = -1e30f, l = 0.f;
    float4 o4[16];
#pragma unroll
    for (int i = 0; i < 16; i++) o4[i] = make_float4(0.f, 0.f, 0.f, 0.f);

    for (int t = 0; t < TXTN; t++) {
        const float4* kp = (const float4*)(sK + t*HDIM);
        float s = 0.f;
#pragma unroll
        for (int i = 0; i < 16; i++) {
            float4 kv = kp[i];
            s = fmaf(q4[i].x, kv.x, s); s = fmaf(q4[i].y, kv.y, s);
            s = fmaf(q4[i].z, kv.z, s); s = fmaf(q4[i].w, kv.w, s);
        }
        s *= 0.125f;
        if (s > m) {
            float c = __expf(m - s);
            l *= c;
#pragma unroll
            for (int i = 0; i < 16; i++) {
                o4[i].x *= c; o4[i].y *= c; o4[i].z *= c; o4[i].w *= c;
            }
            m = s;
        }
        float p = __expf(s - m);
        l += p;
        const float4* vp = (const float4*)(sV + t*HDIM);
#pragma unroll
        for (int i = 0; i < 16; i++) {
            float4 v = vp[i];
            o4[i].x = fmaf(p, v.x, o4[i].x); o4[i].y = fmaf(p, v.y, o4[i].y);
            o4[i].z = fmaf(p, v.z, o4[i].z); o4[i].w = fmaf(p, v.w, o4[i].w);
        }
    }
    const float inv_l = 1.f / l;

    float sip[IPTN];
#pragma unroll
    for (int t = 0; t < IPTN; t++) {
        const float4* kp = (const float4*)(sIK + t*HDIM);
        float s = 0.f;
#pragma unroll
        for (int i = 0; i < 16; i++) {
            float4 kv = kp[i];
            s = fmaf(q4[i].x, kv.x, s); s = fmaf(q4[i].y, kv.y, s);
            s = fmaf(q4[i].z, kv.z, s); s = fmaf(q4[i].w, kv.w, s);
        }
        sip[t] = s * 0.125f;
    }
    const int gr = qi >> 6, gc = qi & 63;
    const int region = (gr < 32) ? ((gc < 32) ? 0 : -1)
                                 : ((gc >= 32) ? 1 : -1);
    if (region == 0) { sip[4] = sip[5] = sip[6] = sip[7] = -1e30f; }
    else if (region == 1) { sip[0] = sip[1] = sip[2] = sip[3] = -1e30f; }

    float m2 = -1e30f;
#pragma unroll
    for (int t = 0; t < IPTN; t++) m2 = fmaxf(m2, sip[t]);
    float p2[IPTN], sum2 = 0.f;
#pragma unroll
    for (int t = 0; t < IPTN; t++) { p2[t] = __expf(sip[t] - m2); sum2 += p2[t]; }

    const float wv  = wbuf[b*QLEN + qi];
    const float wmn = mm[2*b], wmx = mm[2*b + 1];
    float aw = (wv - wmn) / (wmx - wmn);
    aw = (aw < 0.3f) ? 0.f : aw;
    aw *= 0.5f;
    if (region >= 0) aw = aw * 2.f + 1.f;
    const float coeff = aw / sum2;

#pragma unroll
    for (int i = 0; i < 16; i++) {
        float4 acc = make_float4(0.f, 0.f, 0.f, 0.f);
#pragma unroll
        for (int t = 0; t < IPTN; t++) {
            float4 v = ((const float4*)(sIV + t*HDIM))[i];
            acc.x = fmaf(p2[t], v.x, acc.x); acc.y = fmaf(p2[t], v.y, acc.y);
            acc.z = fmaf(p2[t], v.z, acc.z); acc.w = fmaf(p2[t], v.w, acc.w);
        }
        // round to tf32 at store: O-GEMM consumes A with zero in-kernel cvts
        o4[i].x = roundtf(o4[i].x * inv_l + coeff * acc.x);
        o4[i].y = roundtf(o4[i].y * inv_l + coeff * acc.y);
        o4[i].z = roundtf(o4[i].z * inv_l + coeff * acc.z);
        o4[i].w = roundtf(o4[i].w * inv_l + coeff * acc.w);
    }

    __syncthreads();
    float* so = smem;
#pragma unroll
    for (int i = 0; i < 16; i++)
        *(float4*)(so + tid*68 + i*4) = o4[i];
    __syncthreads();

    float* outp = hid + ((size_t)b*QLEN + q0)*HIDD + h*HDIM;
    for (int i4 = tid; i4 < 128*16; i4 += 128) {
        int r = i4 >> 4, c = i4 & 15;
        float4 v = *(const float4*)(so + r*68 + c*4);
        *(float4*)(outp + (size_t)r*HIDD + c*4) = v;
    }
}

// ---------------- host launcher ----------------
extern "C" void kernel_launch(void* const* d_in, const int* in_sizes, int n_in,
                              void* d_out, int out_size)
{
    const float* hs     = (const float*)d_in[0];
    const float* enc    = (const float*)d_in[1];
    const float* Wq     = (const float*)d_in[2];
    const float* Wk     = (const float*)d_in[3];
    const float* Wv     = (const float*)d_in[4];
    const float* Wo     = (const float*)d_in[5];
    const float* bo     = (const float*)d_in[6];
    const float* q_down = (const float*)d_in[7];
    const float* q_up   = (const float*)d_in[8];
    const float* k_down = (const float*)d_in[9];
    const float* k_up   = (const float*)d_in[10];
    const float* v_down = (const float*)d_in[11];
    const float* v_up   = (const float*)d_in[12];
    const float* o_down = (const float*)d_in[13];
    const float* o_up   = (const float*)d_in[14];
    const float* Wk_ip  = (const float*)d_in[15];
    const float* Wv_ip  = (const float*)d_in[16];
    float* out = (float*)d_out;

    float *pWq, *pWqR, *pWkR, *pWvR, *pWoR, *pq, *phid, *pkk, *pvv, *pipk, *pipv;
    float *pehs, *pip, *pipsum, *pipkS, *pwqs, *pw, *pmm;
    cudaGetSymbolAddress((void**)&pWq,   g_Wq);
    cudaGetSymbolAddress((void**)&pWqR,  g_WqR);
    cudaGetSymbolAddress((void**)&pWkR,  g_WkR);
    cudaGetSymbolAddress((void**)&pWvR,  g_WvR);
    cudaGetSymbolAddress((void**)&pWoR,  g_WoR);
    cudaGetSymbolAddress((void**)&pq,    g_q);
    cudaGetSymbolAddress((void**)&phid,  g_hid);
    cudaGetSymbolAddress((void**)&pkk,   g_kk);
    cudaGetSymbolAddress((void**)&pvv,   g_vv);
    cudaGetSymbolAddress((void**)&pipk,  g_ipk);
    cudaGetSymbolAddress((void**)&pipv,  g_ipv);
    cudaGetSymbolAddress((void**)&pehs,  g_ehs);
    cudaGetSymbolAddress((void**)&pip,   g_ip);
    cudaGetSymbolAddress((void**)&pipsum,g_ipsum);
    cudaGetSymbolAddress((void**)&pipkS, g_ipkS);
    cudaGetSymbolAddress((void**)&pwqs,  g_wqs);
    cudaGetSymbolAddress((void**)&pw,    g_w);
    cudaGetSymbolAddress((void**)&pmm,   g_mm);

    // 1) fold LoRA into effective weights (fp32 Wq kept for the exact gate)
    fuse_w_kernel<<<(HIDD*HIDD + 255)/256, 256>>>(Wq, q_down, q_up, pWq, pWqR, HIDD);
    fuse_w_kernel<<<(CDIM*HIDD + 255)/256, 256>>>(Wk, k_down, k_up, nullptr, pWkR, CDIM);
    fuse_w_kernel<<<(CDIM*HIDD + 255)/256, 256>>>(Wv, v_down, v_up, nullptr, pWvR, CDIM);
    fuse_w_kernel<<<(HIDD*HIDD + 255)/256, 256>>>(Wo, o_down, o_up, nullptr, pWoR, HIDD);

    // 2) pack encoder slices
    pack_enc_kernel<<<((NB*TXTN + NB*IPTN)*CDIM + 255)/256, 256>>>(enc, pehs, pip);

    // 3) all projections on tensor cores (TF32)
    gemm_tf32<true,false><<<dim3(HIDD/128, NB*QLEN/128), 128>>>(hs,   pWqR,  pq,   nullptr, NB*QLEN, HIDD, HIDD);
    gemm_tf32<true,false><<<dim3(HIDD/128, 3),           128>>>(pehs, pWkR,  pkk,  nullptr, NB*TXTN, HIDD, CDIM);
    gemm_tf32<true,false><<<dim3(HIDD/128, 3),           128>>>(pehs, pWvR,  pvv,  nullptr, NB*TXTN, HIDD, CDIM);
    gemm_tf32<true,true ><<<dim3(HIDD/128, 1),           128>>>(pip,  Wk_ip, pipk, nullptr, NB*IPTN, HIDD, CDIM);
    gemm_tf32<true,true ><<<dim3(HIDD/128, 1),           128>>>(pip,  Wv_ip, pipv, nullptr, NB*IPTN, HIDD, CDIM);

    // 4) exact fp32 gate: w = 0.125 * hs . ( Wq_fp32 @ ( Wk_ip^T @ sum_t ip_t ) )
    ipsum_kernel<<<(NB*CDIM + 255)/256, 256>>>(pip, pipsum);
    colvec_kernel<<<dim3(HIDD/256, NB), 256>>>(pipsum, Wk_ip, pipkS);
    wqs_matvec_kernel<<<dim3(HIDD/8, NB), 256>>>(pWq, pipkS, pwqs);
    wsum_kernel<<<NB*QLEN/8, 256>>>(hs, pwqs, pw);
    minmax_kernel<<<NB, 256>>>(pw, pmm);

    // 5) fused text + IP attention -> hid (tf32-rounded at store)
    attn_kernel<<<dim3(QLEN/128, NHEAD, NB), 128>>>(pq, pkk, pvv, pipk, pipv, pw, pmm, phid);

    // 6) output projection (+bias), zero in-kernel cvts
    gemm_tf32<false,false><<<dim3(HIDD/128, NB*QLEN/128), 128>>>(phid, pWoR, out, bo, NB*QLEN, HIDD, HIDD);
}

// round 6
// speedup vs baseline: 3.0648x; 1.0786x over previous
#include <cuda_runtime.h>
#include <cstdint>

#define NB    4
#define QLEN  4096
#define HIDD  1024
#define NHEAD 16
#define HDIM  64
#define TXTN  77
#define IPTN  8
#define CDIM  768
#define ENCR  85   // TXT + IPT

// ---------------- scratch (no allocation allowed) ----------------
__device__ float g_Wq  [HIDD*HIDD];   // fp32-exact (gate path)
__device__ float g_WqR [HIDD*HIDD];   // tf32-rounded (GEMM path)
__device__ float g_WkR [CDIM*HIDD];
__device__ float g_WvR [CDIM*HIDD];
__device__ float g_WoR [HIDD*HIDD];
__device__ float g_q   [NB*QLEN*HIDD];
__device__ float g_hid [NB*QLEN*HIDD];   // stored pre-rounded to tf32
__device__ float g_kk  [NB*TXTN*HIDD];
__device__ float g_vv  [NB*TXTN*HIDD];
__device__ float g_ipk [NB*IPTN*HIDD];
__device__ float g_ipv [NB*IPTN*HIDD];
__device__ float g_ehs [NB*TXTN*CDIM];   // stored pre-rounded to tf32
__device__ float g_ip  [NB*IPTN*CDIM];   // exact (gate path reads it)
__device__ float g_ipsum[NB*CDIM];
__device__ float g_ipkS[NB*HIDD];
__device__ float g_wqs [NB*HIDD];
__device__ float g_w   [NB*QLEN];
__device__ float g_mm  [2*NB];

typedef unsigned long long u64;

__device__ __forceinline__ uint32_t f2tf(float x) {
    uint32_t r;
    asm("cvt.rna.tf32.f32 %0, %1;" : "=r"(r) : "f"(x));
    return r;
}
__device__ __forceinline__ float roundtf(float x) {
    return __uint_as_float(f2tf(x));
}
// ---- packed fp32 (FFMA2) helpers ----
__device__ __forceinline__ void fma2(u64& d, u64 a, u64 b) {
    asm("fma.rn.f32x2 %0, %1, %2, %0;" : "+l"(d) : "l"(a), "l"(b));
}
__device__ __forceinline__ void mul2(u64& d, u64 c) {
    asm("mul.rn.f32x2 %0, %0, %1;" : "+l"(d) : "l"(c));
}
__device__ __forceinline__ u64 pack2(float x) {
    u64 r; asm("mov.b64 %0, {%1, %1};" : "=l"(r) : "f"(x)); return r;
}
__device__ __forceinline__ void unpack2(float& lo, float& hi, u64 v) {
    asm("mov.b64 {%0, %1}, %2;" : "=f"(lo), "=f"(hi) : "l"(v));
}

// ---------------- fold rank-4 LoRA into all 4 weights (one launch) ----------
__global__ void fuse_all_kernel(
    const float* __restrict__ Wq, const float* __restrict__ qd, const float* __restrict__ qu,
    const float* __restrict__ Wk, const float* __restrict__ kd, const float* __restrict__ ku,
    const float* __restrict__ Wv, const float* __restrict__ vd, const float* __restrict__ vu,
    const float* __restrict__ Wo, const float* __restrict__ od, const float* __restrict__ ou,
    float* __restrict__ oWqF, float* __restrict__ oWqR,
    float* __restrict__ oWkR, float* __restrict__ oWvR, float* __restrict__ oWoR)
{
    const int NQ = HIDD*HIDD, NK = CDIM*HIDD;
    int idx = blockIdx.x * 256 + threadIdx.x;
    const float *W, *dn, *up;
    float *oF = nullptr, *oR;
    int li;
    if (idx < NQ)              { W=Wq; dn=qd; up=qu; oF=oWqF; oR=oWqR; li=idx; }
    else if (idx < NQ+NK)      { W=Wk; dn=kd; up=ku; oR=oWkR; li=idx-NQ; }
    else if (idx < NQ+2*NK)    { W=Wv; dn=vd; up=vu; oR=oWvR; li=idx-NQ-NK; }
    else if (idx < 2*NQ+2*NK)  { W=Wo; dn=od; up=ou; oR=oWoR; li=idx-NQ-2*NK; }
    else return;
    int r = li >> 10, c = li & 1023;
    float acc = W[li];
#pragma unroll
    for (int j = 0; j < 4; j++)
        acc = fmaf(dn[r*4 + j], up[j*HIDD + c], acc);
    if (oF) oF[li] = acc;
    oR[li] = roundtf(acc);
}

// ---------------- pack encoder slices contiguous ----------------
// ehs is pre-rounded to tf32 (feeds only TF32 GEMMs); ip stays exact (gate).
__global__ void pack_enc_kernel(const float* __restrict__ enc,
                                float* __restrict__ ehs,
                                float* __restrict__ ipb)
{
    int idx = blockIdx.x * 256 + threadIdx.x;
    const int n1 = NB*TXTN*CDIM;
    const int n2 = NB*IPTN*CDIM;
    if (idx < n1) {
        int b = idx / (TXTN*CDIM);
        int rem = idx - b*(TXTN*CDIM);
        int t = rem / CDIM, c = rem - t*CDIM;
        ehs[idx] = roundtf(enc[((size_t)b*ENCR + t)*CDIM + c]);
    } else if (idx < n1 + n2) {
        int k = idx - n1;
        int b = k / (IPTN*CDIM);
        int rem = k - b*(IPTN*CDIM);
        int t = rem / CDIM, c = rem - t*CDIM;
        ipb[k] = enc[((size_t)b*ENCR + TXTN + t)*CDIM + c];
    }
}

// ================= TF32 tensor-core GEMM: C[M,N] = A[M,K] @ B[K,N] (+bias) ====
#define APAD 20
#define BPAD 136

__device__ __forceinline__ void mma_tf32(float* c, const uint32_t* a, const uint32_t* b) {
    asm volatile("mma.sync.aligned.m16n8k8.row.col.f32.tf32.tf32.f32 "
        "{%0,%1,%2,%3}, {%4,%5,%6,%7}, {%8,%9}, {%0,%1,%2,%3};"
        : "+f"(c[0]), "+f"(c[1]), "+f"(c[2]), "+f"(c[3])
        : "r"(a[0]), "r"(a[1]), "r"(a[2]), "r"(a[3]), "r"(b[0]), "r"(b[1]));
}
__device__ __forceinline__ void cp16(uint32_t s, const void* g) {
    asm volatile("cp.async.ca.shared.global [%0], [%1], 16;" :: "r"(s), "l"(g));
}
__device__ __forceinline__ void cp_commit() {
    asm volatile("cp.async.commit_group;");
}
template<int N_> __device__ __forceinline__ void cp_wait() {
    asm volatile("cp.async.wait_group %0;" :: "n"(N_));
}
template<bool CVT>
__device__ __forceinline__ uint32_t ldfrag(const float* p) {
    float v = *p;
    return CVT ? f2tf(v) : __float_as_uint(v);
}

template<bool CVTA, bool CVTB>
__global__ __launch_bounds__(128, 2) void gemm_tf32(
    const float* __restrict__ A, const float* __restrict__ B,
    float* __restrict__ C, const float* __restrict__ bias,
    int M, int N, int K)
{
    __shared__ float As[2][128*APAD];
    __shared__ float Bs[2][16*BPAD];

    const int tid  = threadIdx.x;
    const int lane = tid & 31;
    const int warp = tid >> 5;
    const int wm = (warp >> 1) * 64;
    const int wn = (warp & 1) * 64;
    const int bx = blockIdx.x, by = blockIdx.y;

    const float* Bg = B + bx * 128;

    const int a_colv = tid & 3;
    const int a_rowb = tid >> 2;
    const int b_colv = tid & 31;
    const int b_rowb = tid >> 5;

    const uint32_t as0 = (uint32_t)__cvta_generic_to_shared(&As[0][0]);
    const uint32_t bs0 = (uint32_t)__cvta_generic_to_shared(&Bs[0][0]);

    float acc[4][8][4];
#pragma unroll
    for (int i = 0; i < 4; i++)
#pragma unroll
        for (int j = 0; j < 8; j++)
#pragma unroll
            for (int r = 0; r < 4; r++) acc[i][j][r] = 0.f;

    auto load_stage = [&](int k0, int buf) {
        uint32_t asb = as0 + (uint32_t)buf * (128*APAD*4);
        uint32_t bsb = bs0 + (uint32_t)buf * (16*BPAD*4);
#pragma unroll
        for (int i = 0; i < 4; i++) {
            int row = a_rowb + i*32;
            int rg = by*128 + row; if (rg > M-1) rg = M-1;
            cp16(asb + (uint32_t)(row*APAD + a_colv*4)*4,
                 A + (size_t)rg*K + k0 + a_colv*4);
        }
#pragma unroll
        for (int i = 0; i < 4; i++) {
            int row = b_rowb + i*4;
            cp16(bsb + (uint32_t)(row*BPAD + b_colv*4)*4,
                 Bg + (size_t)(k0 + row)*N + b_colv*4);
        }
    };

    const int nstage = K / 16;
    load_stage(0, 0);
    cp_commit();

    int buf = 0;
    for (int s = 0; s < nstage; s++) {
        if (s + 1 < nstage) {
            load_stage((s + 1)*16, buf ^ 1);
            cp_commit();
            cp_wait<1>();
        } else {
            cp_wait<0>();
        }
        __syncthreads();

        const float* as = As[buf];
        const float* bs = Bs[buf];
#pragma unroll
        for (int ks = 0; ks < 16; ks += 8) {
            uint32_t af[4][4];
#pragma unroll
            for (int im = 0; im < 4; im++) {
                const float* ap = as + (wm + im*16 + (lane >> 2))*APAD + ks + (lane & 3);
                af[im][0] = ldfrag<CVTA>(ap);
                af[im][1] = ldfrag<CVTA>(ap + 8*APAD);
                af[im][2] = ldfrag<CVTA>(ap + 4);
                af[im][3] = ldfrag<CVTA>(ap + 8*APAD + 4);
            }
            uint32_t bf[8][2];
#pragma unroll
            for (int jn = 0; jn < 8; jn++) {
                const float* bp = bs + (ks + (lane & 3))*BPAD + wn + jn*8 + (lane >> 2);
                bf[jn][0] = ldfrag<CVTB>(bp);
                bf[jn][1] = ldfrag<CVTB>(bp + 4*BPAD);
            }
#pragma unroll
            for (int im = 0; im < 4; im++)
#pragma unroll
                for (int jn = 0; jn < 8; jn++)
                    mma_tf32(acc[im][jn], af[im], bf[jn]);
        }
        __syncthreads();
        buf ^= 1;
    }

#pragma unroll
    for (int im = 0; im < 4; im++) {
#pragma unroll
        for (int jn = 0; jn < 8; jn++) {
            int r = by*128 + wm + im*16 + (lane >> 2);
            int c = bx*128 + wn + jn*8 + 2*(lane & 3);
            float2 v0 = make_float2(acc[im][jn][0], acc[im][jn][1]);
            float2 v1 = make_float2(acc[im][jn][2], acc[im][jn][3]);
            if (bias) {
                float2 bv = *(const float2*)(bias + c);
                v0.x += bv.x; v0.y += bv.y;
                v1.x += bv.x; v1.y += bv.y;
            }
            if (r < M)     *(float2*)(C + (size_t)r*N + c)       = v0;
            if (r + 8 < M) *(float2*)(C + (size_t)(r + 8)*N + c) = v1;
        }
    }
}

// ---------------- exact fp32 gate path ----------------
__global__ void ipsum_kernel(const float* __restrict__ ip, float* __restrict__ out)
{
    int idx = blockIdx.x * 256 + threadIdx.x;
    if (idx >= NB * CDIM) return;
    int b = idx / CDIM, c = idx - b*CDIM;
    float s = 0.f;
#pragma unroll
    for (int t = 0; t < IPTN; t++)
        s += ip[((size_t)b*IPTN + t)*CDIM + c];
    out[idx] = s;
}

__global__ __launch_bounds__(256) void colvec_kernel(
    const float* __restrict__ s, const float* __restrict__ W,
    float* __restrict__ out)
{
    __shared__ float ss[CDIM];
    const int b = blockIdx.y;
    const int j = blockIdx.x * 256 + threadIdx.x;
    for (int i = threadIdx.x; i < CDIM; i += 256) ss[i] = s[b*CDIM + i];
    __syncthreads();
    float acc = 0.f;
#pragma unroll 8
    for (int i = 0; i < CDIM; i++)
        acc = fmaf(ss[i], W[(size_t)i*HIDD + j], acc);
    out[b*HIDD + j] = acc;
}

__global__ __launch_bounds__(256) void wqs_matvec_kernel(
    const float* __restrict__ W, const float* __restrict__ s,
    float* __restrict__ v)
{
    __shared__ float sv[HIDD];
    const int b = blockIdx.y;
    for (int i = threadIdx.x; i < HIDD; i += 256) sv[i] = s[b*HIDD + i];
    __syncthreads();
    const int warp = threadIdx.x >> 5, lane = threadIdx.x & 31;
    const int row = blockIdx.x * 8 + warp;
    const float* wr = W + (size_t)row * HIDD;
    float acc = 0.f;
#pragma unroll
    for (int i = 0; i < 32; i++)
        acc = fmaf(wr[lane + 32*i], sv[lane + 32*i], acc);
#pragma unroll
    for (int off = 16; off > 0; off >>= 1)
        acc += __shfl_xor_sync(0xffffffffu, acc, off);
    if (lane == 0) v[b*HIDD + row] = acc;
}

__global__ __launch_bounds__(256) void wsum_kernel(const float* __restrict__ hs,
                                                   const float* __restrict__ vb,
                                                   float* __restrict__ w)
{
    __shared__ float sk[HIDD];
    const int row0 = blockIdx.x * 8;
    const int b = row0 / QLEN;
    for (int i = threadIdx.x; i < HIDD; i += 256) sk[i] = vb[b*HIDD + i];
    __syncthreads();
    const int warp = threadIdx.x >> 5, lane = threadIdx.x & 31;
    const int row = row0 + warp;
    const float* qr = hs + (size_t)row * HIDD;
    float s = 0.f;
#pragma unroll
    for (int i = 0; i < 32; i++)
        s = fmaf(qr[lane + 32*i], sk[lane + 32*i], s);
#pragma unroll
    for (int off = 16; off > 0; off >>= 1)
        s += __shfl_xor_sync(0xffffffffu, s, off);
    if (lane == 0) w[row] = 0.125f * s;
}

__global__ void minmax_kernel(const float* __restrict__ w, float* __restrict__ mm)
{
    __shared__ float smn[256], smx[256];
    const int b = blockIdx.x, tid = threadIdx.x;
    float mn = 1e30f, mx = -1e30f;
    for (int i = tid; i < QLEN; i += 256) {
        float v = w[b*QLEN + i];
        mn = fminf(mn, v); mx = fmaxf(mx, v);
    }
    smn[tid] = mn; smx[tid] = mx;
    __syncthreads();
    for (int s = 128; s > 0; s >>= 1) {
        if (tid < s) {
            smn[tid] = fminf(smn[tid], smn[tid + s]);
            smx[tid] = fmaxf(smx[tid], smx[tid + s]);
        }
        __syncthreads();
    }
    if (tid == 0) { mm[2*b] = smn[0]; mm[2*b + 1] = smx[0]; }
}

// ---------------- fused attention (packed fp32 / FFMA2 throughout) ----------
__global__ __launch_bounds__(128) void attn_kernel(
    const float* __restrict__ qb,
    const float* __restrict__ kk,
    const float* __restrict__ vv,
    const float* __restrict__ ipk,
    const float* __restrict__ ipv,
    const float* __restrict__ wbuf,
    const float* __restrict__ mm,
    float* __restrict__ hid)
{
    __shared__ __align__(16) float smem[TXTN*HDIM*2 + IPTN*HDIM*2];
    float* sK  = smem;
    float* sV  = smem + TXTN*HDIM;
    float* sIK = smem + 2*TXTN*HDIM;
    float* sIV = sIK + IPTN*HDIM;

    const int tid = threadIdx.x;
    const int b = blockIdx.z, h = blockIdx.y, q0 = blockIdx.x * 128;

    const size_t kvbase = ((size_t)b*TXTN)*HIDD + h*HDIM;
    for (int i = tid; i < TXTN*HDIM; i += 128) {
        int t = i >> 6, d = i & 63;
        sK[i] = kk[kvbase + (size_t)t*HIDD + d];
        sV[i] = vv[kvbase + (size_t)t*HIDD + d];
    }
    const size_t ipbase = ((size_t)b*IPTN)*HIDD + h*HDIM;
    for (int i = tid; i < IPTN*HDIM; i += 128) {
        int t = i >> 6, d = i & 63;
        sIK[i] = ipk[ipbase + (size_t)t*HIDD + d];
        sIV[i] = ipv[ipbase + (size_t)t*HIDD + d];
    }
    __syncthreads();

    const int qi = q0 + tid;

    // load q (64 floats) as 32 packed pairs, pre-scaled by 0.125 (exact pow2)
    u64 q2[32];
    {
        const ulonglong2* qp = (const ulonglong2*)(qb + ((size_t)b*QLEN + qi)*HIDD + h*HDIM);
        const u64 eighth = pack2(0.125f);
#pragma unroll
        for (int i = 0; i < 16; i++) {
            ulonglong2 v = qp[i];
            q2[2*i]   = v.x;
            q2[2*i+1] = v.y;
        }
#pragma unroll
        for (int i = 0; i < 32; i++) mul2(q2[i], eighth);
    }

    // ---- text attention, online softmax (packed accumulate) ----
    float m = -1e30f, l = 0.f;
    u64 o2[32];
#pragma unroll
    for (int i = 0; i < 32; i++) o2[i] = 0ULL;

    for (int t = 0; t < TXTN; t++) {
        const u64* kp = (const u64*)(sK + t*HDIM);
        u64 a = 0ULL;
#pragma unroll
        for (int i = 0; i < 32; i++) fma2(a, q2[i], kp[i]);
        float lo, hi; unpack2(lo, hi, a);
        float s = lo + hi;
        if (s > m) {
            float c = __expf(m - s);
            l *= c;
            u64 cc = pack2(c);
#pragma unroll
            for (int i = 0; i < 32; i++) mul2(o2[i], cc);
            m = s;
        }
        float p = __expf(s - m);
        l += p;
        u64 pp = pack2(p);
        const u64* vp = (const u64*)(sV + t*HDIM);
#pragma unroll
        for (int i = 0; i < 32; i++) fma2(o2[i], pp, vp[i]);
    }
    const float inv_l = 1.f / l;

    // ---- IP scores (q2 already carries the 0.125 scale) ----
    float sip[IPTN];
#pragma unroll
    for (int t = 0; t < IPTN; t++) {
        const u64* kp = (const u64*)(sIK + t*HDIM);
        u64 a = 0ULL;
#pragma unroll
        for (int i = 0; i < 32; i++) fma2(a, q2[i], kp[i]);
        float lo, hi; unpack2(lo, hi, a);
        sip[t] = lo + hi;
    }
    const int gr = qi >> 6, gc = qi & 63;
    const int region = (gr < 32) ? ((gc < 32) ? 0 : -1)
                                 : ((gc >= 32) ? 1 : -1);
    if (region == 0) { sip[4] = sip[5] = sip[6] = sip[7] = -1e30f; }
    else if (region == 1) { sip[0] = sip[1] = sip[2] = sip[3] = -1e30f; }

    float m2 = -1e30f;
#pragma unroll
    for (int t = 0; t < IPTN; t++) m2 = fmaxf(m2, sip[t]);
    float p2[IPTN], sum2 = 0.f;
#pragma unroll
    for (int t = 0; t < IPTN; t++) { p2[t] = __expf(sip[t] - m2); sum2 += p2[t]; }

    const float wv  = wbuf[b*QLEN + qi];
    const float wmn = mm[2*b], wmx = mm[2*b + 1];
    float aw = (wv - wmn) / (wmx - wmn);
    aw = (aw < 0.3f) ? 0.f : aw;
    aw *= 0.5f;
    if (region >= 0) aw = aw * 2.f + 1.f;
    const float coeff = aw / sum2;

    u64 pp2[IPTN];
#pragma unroll
    for (int t = 0; t < IPTN; t++) pp2[t] = pack2(p2[t]);
    const u64 invl2 = pack2(inv_l);
    const u64 co2   = pack2(coeff);

    // ---- combine + round-to-tf32 + stage through smem ----
    __syncthreads();                 // all threads done reading sK/sV
    float* so = smem;                // staging region (does not overlap sIV)
    const u64* iv = (const u64*)sIV;
#pragma unroll
    for (int i = 0; i < 32; i++) {
        u64 ipa = 0ULL;
#pragma unroll
        for (int t = 0; t < IPTN; t++) fma2(ipa, pp2[t], iv[t*32 + i]);
        mul2(o2[i], invl2);          // o *= 1/l
        fma2(o2[i], co2, ipa);       // o += coeff * ip
        float lo, hi; unpack2(lo, hi, o2[i]);
        so[tid*68 + 2*i]     = roundtf(lo);
        so[tid*68 + 2*i + 1] = roundtf(hi);
    }
    __syncthreads();

    float* outp = hid + ((size_t)b*QLEN + q0)*HIDD + h*HDIM;
    for (int i4 = tid; i4 < 128*16; i4 += 128) {
        int r = i4 >> 4, c = i4 & 15;
        float4 v = *(const float4*)(so + r*68 + c*4);
        *(float4*)(outp + (size_t)r*HIDD + c*4) = v;
    }
}

// ---------------- host launcher ----------------
extern "C" void kernel_launch(void* const* d_in, const int* in_sizes, int n_in,
                              void* d_out, int out_size)
{
    const float* hs     = (const float*)d_in[0];
    const float* enc    = (const float*)d_in[1];
    const float* Wq     = (const float*)d_in[2];
    const float* Wk     = (const float*)d_in[3];
    const float* Wv     = (const float*)d_in[4];
    const float* Wo     = (const float*)d_in[5];
    const float* bo     = (const float*)d_in[6];
    const float* q_down = (const float*)d_in[7];
    const float* q_up   = (const float*)d_in[8];
    const float* k_down = (const float*)d_in[9];
    const float* k_up   = (const float*)d_in[10];
    const float* v_down = (const float*)d_in[11];
    const float* v_up   = (const float*)d_in[12];
    const float* o_down = (const float*)d_in[13];
    const float* o_up   = (const float*)d_in[14];
    const float* Wk_ip  = (const float*)d_in[15];
    const float* Wv_ip  = (const float*)d_in[16];
    float* out = (float*)d_out;

    float *pWq, *pWqR, *pWkR, *pWvR, *pWoR, *pq, *phid, *pkk, *pvv, *pipk, *pipv;
    float *pehs, *pip, *pipsum, *pipkS, *pwqs, *pw, *pmm;
    cudaGetSymbolAddress((void**)&pWq,   g_Wq);
    cudaGetSymbolAddress((void**)&pWqR,  g_WqR);
    cudaGetSymbolAddress((void**)&pWkR,  g_WkR);
    cudaGetSymbolAddress((void**)&pWvR,  g_WvR);
    cudaGetSymbolAddress((void**)&pWoR,  g_WoR);
    cudaGetSymbolAddress((void**)&pq,    g_q);
    cudaGetSymbolAddress((void**)&phid,  g_hid);
    cudaGetSymbolAddress((void**)&pkk,   g_kk);
    cudaGetSymbolAddress((void**)&pvv,   g_vv);
    cudaGetSymbolAddress((void**)&pipk,  g_ipk);
    cudaGetSymbolAddress((void**)&pipv,  g_ipv);
    cudaGetSymbolAddress((void**)&pehs,  g_ehs);
    cudaGetSymbolAddress((void**)&pip,   g_ip);
    cudaGetSymbolAddress((void**)&pipsum,g_ipsum);
    cudaGetSymbolAddress((void**)&pipkS, g_ipkS);
    cudaGetSymbolAddress((void**)&pwqs,  g_wqs);
    cudaGetSymbolAddress((void**)&pw,    g_w);
    cudaGetSymbolAddress((void**)&pmm,   g_mm);

    // 1) fold LoRA into effective weights (single launch)
    const int fuse_elems = 2*HIDD*HIDD + 2*CDIM*HIDD;
    fuse_all_kernel<<<(fuse_elems + 255)/256, 256>>>(
        Wq, q_down, q_up, Wk, k_down, k_up, Wv, v_down, v_up, Wo, o_down, o_up,
        pWq, pWqR, pWkR, pWvR, pWoR);

    // 2) pack encoder slices (ehs tf32-rounded, ip exact)
    pack_enc_kernel<<<((NB*TXTN + NB*IPTN)*CDIM + 255)/256, 256>>>(enc, pehs, pip);

    // 3) all projections on tensor cores (TF32)
    gemm_tf32<true ,false><<<dim3(HIDD/128, NB*QLEN/128), 128>>>(hs,   pWqR,  pq,   nullptr, NB*QLEN, HIDD, HIDD);
    gemm_tf32<false,false><<<dim3(HIDD/128, 3),           128>>>(pehs, pWkR,  pkk,  nullptr, NB*TXTN, HIDD, CDIM);
    gemm_tf32<false,false><<<dim3(HIDD/128, 3),           128>>>(pehs, pWvR,  pvv,  nullptr, NB*TXTN, HIDD, CDIM);
    gemm_tf32<true ,true ><<<dim3(HIDD/128, 1),           128>>>(pip,  Wk_ip, pipk, nullptr, NB*IPTN, HIDD, CDIM);
    gemm_tf32<true ,true ><<<dim3(HIDD/128, 1),           128>>>(pip,  Wv_ip, pipv, nullptr, NB*IPTN, HIDD, CDIM);

    // 4) exact fp32 gate: w = 0.125 * hs . ( Wq_fp32 @ ( Wk_ip^T @ sum_t ip_t ) )
    ipsum_kernel<<<(NB*CDIM + 255)/256, 256>>>(pip, pipsum);
    colvec_kernel<<<dim3(HIDD/256, NB), 256>>>(pipsum, Wk_ip, pipkS);
    wqs_matvec_kernel<<<dim3(HIDD/8, NB), 256>>>(pWq, pipkS, pwqs);
    wsum_kernel<<<NB*QLEN/8, 256>>>(hs, pwqs, pw);
    minmax_kernel<<<NB, 256>>>(pw, pmm);

    // 5) fused text + IP attention -> hid (tf32-rounded at store)
    attn_kernel<<<dim3(QLEN/128, NHEAD, NB), 128>>>(pq, pkk, pvv, pipk, pipv, pw, pmm, phid);

    // 6) output projection (+bias), zero in-kernel cvts
    gemm_tf32<false,false><<<dim3(HIDD/128, NB*QLEN/128), 128>>>(phid, pWoR, out, bo, NB*QLEN, HIDD, HIDD);
}

// round 8
// speedup vs baseline: 3.4925x; 1.1396x over previous
#include <cuda_runtime.h>
#include <cstdint>

#define NB    4
#define QLEN  4096
#define HIDD  1024
#define NHEAD 16
#define HDIM  64
#define TXTN  77
#define IPTN  8
#define CDIM  768
#define ENCR  85   // TXT + IPT

// ---------------- scratch (no allocation allowed) ----------------
__device__ float g_Wq  [HIDD*HIDD];   // fp32-exact (gate path)
__device__ float g_WqR [HIDD*HIDD];   // tf32-rounded (GEMM path)
__device__ float g_WkR [CDIM*HIDD];
__device__ float g_WvR [CDIM*HIDD];
__device__ float g_WoR [HIDD*HIDD];
__device__ float g_q   [NB*QLEN*HIDD];
__device__ float g_hid [NB*QLEN*HIDD];   // stored pre-rounded to tf32
__device__ float g_kk  [NB*TXTN*HIDD];
__device__ float g_vv  [NB*TXTN*HIDD];
__device__ float g_ipk [NB*IPTN*HIDD];
__device__ float g_ipv [NB*IPTN*HIDD];
__device__ float g_ehs [NB*TXTN*CDIM];   // stored pre-rounded to tf32
__device__ float g_ip  [NB*IPTN*CDIM];   // exact (gate path reads it)
__device__ float g_ipsum[NB*CDIM];
__device__ float g_ipkS[NB*HIDD];
__device__ float g_wqs [NB*HIDD];
__device__ float g_w   [NB*QLEN];
__device__ float g_mm  [2*NB];

typedef unsigned long long u64;

__device__ __forceinline__ uint32_t f2tf(float x) {
    uint32_t r;
    asm("cvt.rna.tf32.f32 %0, %1;" : "=r"(r) : "f"(x));
    return r;
}
__device__ __forceinline__ float roundtf(float x) {
    return __uint_as_float(f2tf(x));
}
// ---- packed fp32 (FFMA2) helpers ----
__device__ __forceinline__ void fma2(u64& d, u64 a, u64 b) {
    asm("fma.rn.f32x2 %0, %1, %2, %0;" : "+l"(d) : "l"(a), "l"(b));
}
__device__ __forceinline__ void mul2(u64& d, u64 c) {
    asm("mul.rn.f32x2 %0, %0, %1;" : "+l"(d) : "l"(c));
}
__device__ __forceinline__ u64 pack2(float x) {
    u64 r; asm("mov.b64 %0, {%1, %1};" : "=l"(r) : "f"(x)); return r;
}
__device__ __forceinline__ void unpack2(float& lo, float& hi, u64 v) {
    asm("mov.b64 {%0, %1}, %2;" : "=f"(lo), "=f"(hi) : "l"(v));
}

// ---------------- fold rank-4 LoRA into all 4 weights (one launch) ----------
__global__ void fuse_all_kernel(
    const float* __restrict__ Wq, const float* __restrict__ qd, const float* __restrict__ qu,
    const float* __restrict__ Wk, const float* __restrict__ kd, const float* __restrict__ ku,
    const float* __restrict__ Wv, const float* __restrict__ vd, const float* __restrict__ vu,
    const float* __restrict__ Wo, const float* __restrict__ od, const float* __restrict__ ou,
    float* __restrict__ oWqF, float* __restrict__ oWqR,
    float* __restrict__ oWkR, float* __restrict__ oWvR, float* __restrict__ oWoR)
{
    const int NQ = HIDD*HIDD, NK = CDIM*HIDD;
    int idx = blockIdx.x * 256 + threadIdx.x;
    const float *W, *dn, *up;
    float *oF = nullptr, *oR;
    int li;
    if (idx < NQ)              { W=Wq; dn=qd; up=qu; oF=oWqF; oR=oWqR; li=idx; }
    else if (idx < NQ+NK)      { W=Wk; dn=kd; up=ku; oR=oWkR; li=idx-NQ; }
    else if (idx < NQ+2*NK)    { W=Wv; dn=vd; up=vu; oR=oWvR; li=idx-NQ-NK; }
    else if (idx < 2*NQ+2*NK)  { W=Wo; dn=od; up=ou; oR=oWoR; li=idx-NQ-2*NK; }
    else return;
    int r = li >> 10, c = li & 1023;
    float acc = W[li];
#pragma unroll
    for (int j = 0; j < 4; j++)
        acc = fmaf(dn[r*4 + j], up[j*HIDD + c], acc);
    if (oF) oF[li] = acc;
    oR[li] = roundtf(acc);
}

// ---------------- pack encoder slices contiguous ----------------
__global__ void pack_enc_kernel(const float* __restrict__ enc,
                                float* __restrict__ ehs,
                                float* __restrict__ ipb)
{
    int idx = blockIdx.x * 256 + threadIdx.x;
    const int n1 = NB*TXTN*CDIM;
    const int n2 = NB*IPTN*CDIM;
    if (idx < n1) {
        int b = idx / (TXTN*CDIM);
        int rem = idx - b*(TXTN*CDIM);
        int t = rem / CDIM, c = rem - t*CDIM;
        ehs[idx] = roundtf(enc[((size_t)b*ENCR + t)*CDIM + c]);
    } else if (idx < n1 + n2) {
        int k = idx - n1;
        int b = k / (IPTN*CDIM);
        int rem = k - b*(IPTN*CDIM);
        int t = rem / CDIM, c = rem - t*CDIM;
        ipb[k] = enc[((size_t)b*ENCR + TXTN + t)*CDIM + c];
    }
}

// ================= TF32 tensor-core GEMM body =================================
#define APAD 20
#define BPAD 136

__device__ __forceinline__ void mma_tf32(float* c, const uint32_t* a, const uint32_t* b) {
    asm volatile("mma.sync.aligned.m16n8k8.row.col.f32.tf32.tf32.f32 "
        "{%0,%1,%2,%3}, {%4,%5,%6,%7}, {%8,%9}, {%0,%1,%2,%3};"
        : "+f"(c[0]), "+f"(c[1]), "+f"(c[2]), "+f"(c[3])
        : "r"(a[0]), "r"(a[1]), "r"(a[2]), "r"(a[3]), "r"(b[0]), "r"(b[1]));
}
__device__ __forceinline__ void cp16(uint32_t s, const void* g) {
    asm volatile("cp.async.ca.shared.global [%0], [%1], 16;" :: "r"(s), "l"(g));
}
__device__ __forceinline__ void cp_commit() {
    asm volatile("cp.async.commit_group;");
}
template<int N_> __device__ __forceinline__ void cp_wait() {
    asm volatile("cp.async.wait_group %0;" :: "n"(N_));
}
template<bool CVT>
__device__ __forceinline__ uint32_t ldfrag(const float* p) {
    float v = *p;
    return CVT ? f2tf(v) : __float_as_uint(v);
}

template<bool CVTA, bool CVTB>
__device__ __forceinline__ void gemm_body(
    const float* __restrict__ A, const float* __restrict__ B,
    float* __restrict__ C, const float* __restrict__ bias,
    int M, int N, int K, int bx, int by)
{
    __shared__ float As[2][128*APAD];
    __shared__ float Bs[2][16*BPAD];

    const int tid  = threadIdx.x;
    const int lane = tid & 31;
    const int warp = tid >> 5;
    const int wm = (warp >> 1) * 64;
    const int wn = (warp & 1) * 64;

    const float* Bg = B + bx * 128;

    const int a_colv = tid & 3;
    const int a_rowb = tid >> 2;
    const int b_colv = tid & 31;
    const int b_rowb = tid >> 5;

    const uint32_t as0 = (uint32_t)__cvta_generic_to_shared(&As[0][0]);
    const uint32_t bs0 = (uint32_t)__cvta_generic_to_shared(&Bs[0][0]);

    float acc[4][8][4];
#pragma unroll
    for (int i = 0; i < 4; i++)
#pragma unroll
        for (int j = 0; j < 8; j++)
#pragma unroll
            for (int r = 0; r < 4; r++) acc[i][j][r] = 0.f;

    auto load_stage = [&](int k0, int buf) {
        uint32_t asb = as0 + (uint32_t)buf * (128*APAD*4);
        uint32_t bsb = bs0 + (uint32_t)buf * (16*BPAD*4);
#pragma unroll
        for (int i = 0; i < 4; i++) {
            int row = a_rowb + i*32;
            int rg = by*128 + row; if (rg > M-1) rg = M-1;
            cp16(asb + (uint32_t)(row*APAD + a_colv*4)*4,
                 A + (size_t)rg*K + k0 + a_colv*4);
        }
#pragma unroll
        for (int i = 0; i < 4; i++) {
            int row = b_rowb + i*4;
            cp16(bsb + (uint32_t)(row*BPAD + b_colv*4)*4,
                 Bg + (size_t)(k0 + row)*N + b_colv*4);
        }
    };

    const int nstage = K / 16;
    load_stage(0, 0);
    cp_commit();

    int buf = 0;
    for (int s = 0; s < nstage; s++) {
        if (s + 1 < nstage) {
            load_stage((s + 1)*16, buf ^ 1);
            cp_commit();
            cp_wait<1>();
        } else {
            cp_wait<0>();
        }
        __syncthreads();

        const float* as = As[buf];
        const float* bs = Bs[buf];
#pragma unroll
        for (int ks = 0; ks < 16; ks += 8) {
            uint32_t af[4][4];
#pragma unroll
            for (int im = 0; im < 4; im++) {
                const float* ap = as + (wm + im*16 + (lane >> 2))*APAD + ks + (lane & 3);
                af[im][0] = ldfrag<CVTA>(ap);
                af[im][1] = ldfrag<CVTA>(ap + 8*APAD);
                af[im][2] = ldfrag<CVTA>(ap + 4);
                af[im][3] = ldfrag<CVTA>(ap + 8*APAD + 4);
            }
            uint32_t bf[8][2];
#pragma unroll
            for (int jn = 0; jn < 8; jn++) {
                const float* bp = bs + (ks + (lane & 3))*BPAD + wn + jn*8 + (lane >> 2);
                bf[jn][0] = ldfrag<CVTB>(bp);
                bf[jn][1] = ldfrag<CVTB>(bp + 4*BPAD);
            }
#pragma unroll
            for (int im = 0; im < 4; im++)
#pragma unroll
                for (int jn = 0; jn < 8; jn++)
                    mma_tf32(acc[im][jn], af[im], bf[jn]);
        }
        __syncthreads();
        buf ^= 1;
    }

#pragma unroll
    for (int im = 0; im < 4; im++) {
#pragma unroll
        for (int jn = 0; jn < 8; jn++) {
            int r = by*128 + wm + im*16 + (lane >> 2);
            int c = bx*128 + wn + jn*8 + 2*(lane & 3);
            float2 v0 = make_float2(acc[im][jn][0], acc[im][jn][1]);
            float2 v1 = make_float2(acc[im][jn][2], acc[im][jn][3]);
            if (bias) {
                float2 bv = *(const float2*)(bias + c);
                v0.x += bv.x; v0.y += bv.y;
                v1.x += bv.x; v1.y += bv.y;
            }
            if (r < M)     *(float2*)(C + (size_t)r*N + c)       = v0;
            if (r + 8 < M) *(float2*)(C + (size_t)(r + 8)*N + c) = v1;
        }
    }
}

template<bool CVTA, bool CVTB>
__global__ __launch_bounds__(128, 2) void gemm_tf32(
    const float* __restrict__ A, const float* __restrict__ B,
    float* __restrict__ C, const float* __restrict__ bias,
    int M, int N, int K)
{
    gemm_body<CVTA, CVTB>(A, B, C, bias, M, N, K, blockIdx.x, blockIdx.y);
}

// Merged enc-K/V + ip-K/V projections: grid (8, 4, 2)
//   y in 0..2: enc rows (M=308), y==3: ip rows (M=32); z: 0 = K-weight, 1 = V-weight
__global__ __launch_bounds__(128, 2) void gemm_encip(
    const float* __restrict__ ehs, const float* __restrict__ ipb,
    const float* __restrict__ WkR, const float* __restrict__ WvR,
    const float* __restrict__ Wk_ip, const float* __restrict__ Wv_ip,
    float* __restrict__ kk, float* __restrict__ vv,
    float* __restrict__ ipk, float* __restrict__ ipv)
{
    const int y = blockIdx.y, z = blockIdx.z;
    const float *A, *B; float* C; int M, by;
    if (y < 3) { A = ehs; M = NB*TXTN; by = y; B = z ? WvR  : WkR;   C = z ? vv  : kk;  }
    else       { A = ipb; M = NB*IPTN; by = 0; B = z ? Wv_ip : Wk_ip; C = z ? ipv : ipk; }
    // cvt.rna on pre-rounded values is the identity, so <true,true> is safe for all paths
    gemm_body<true, true>(A, B, C, nullptr, M, HIDD, CDIM, blockIdx.x, by);
}

// ---------------- exact fp32 gate path ----------------
__global__ void ipsum_kernel(const float* __restrict__ ip, float* __restrict__ out)
{
    int idx = blockIdx.x * 256 + threadIdx.x;
    if (idx >= NB * CDIM) return;
    int b = idx / CDIM, c = idx - b*CDIM;
    float s = 0.f;
#pragma unroll
    for (int t = 0; t < IPTN; t++)
        s += ip[((size_t)b*IPTN + t)*CDIM + c];
    out[idx] = s;
}

__global__ __launch_bounds__(256) void colvec_kernel(
    const float* __restrict__ s, const float* __restrict__ W,
    float* __restrict__ out)
{
    __shared__ float ss[CDIM];
    const int b = blockIdx.y;
    const int j = blockIdx.x * 256 + threadIdx.x;
    for (int i = threadIdx.x; i < CDIM; i += 256) ss[i] = s[b*CDIM + i];
    __syncthreads();
    float acc = 0.f;
#pragma unroll 8
    for (int i = 0; i < CDIM; i++)
        acc = fmaf(ss[i], W[(size_t)i*HIDD + j], acc);
    out[b*HIDD + j] = acc;
}

__global__ __launch_bounds__(256) void wqs_matvec_kernel(
    const float* __restrict__ W, const float* __restrict__ s,
    float* __restrict__ v)
{
    __shared__ float sv[HIDD];
    const int b = blockIdx.y;
    for (int i = threadIdx.x; i < HIDD; i += 256) sv[i] = s[b*HIDD + i];
    __syncthreads();
    const int warp = threadIdx.x >> 5, lane = threadIdx.x & 31;
    const int row = blockIdx.x * 8 + warp;
    const float* wr = W + (size_t)row * HIDD;
    float acc = 0.f;
#pragma unroll
    for (int i = 0; i < 32; i++)
        acc = fmaf(wr[lane + 32*i], sv[lane + 32*i], acc);
#pragma unroll
    for (int off = 16; off > 0; off >>= 1)
        acc += __shfl_xor_sync(0xffffffffu, acc, off);
    if (lane == 0) v[b*HIDD + row] = acc;
}

__global__ __launch_bounds__(256) void wsum_kernel(const float* __restrict__ hs,
                                                   const float* __restrict__ vb,
                                                   float* __restrict__ w)
{
    __shared__ float sk[HIDD];
    const int row0 = blockIdx.x * 8;
    const int b = row0 / QLEN;
    for (int i = threadIdx.x; i < HIDD; i += 256) sk[i] = vb[b*HIDD + i];
    __syncthreads();
    const int warp = threadIdx.x >> 5, lane = threadIdx.x & 31;
    const int row = row0 + warp;
    const float* qr = hs + (size_t)row * HIDD;
    float s = 0.f;
#pragma unroll
    for (int i = 0; i < 32; i++)
        s = fmaf(qr[lane + 32*i], sk[lane + 32*i], s);
#pragma unroll
    for (int off = 16; off > 0; off >>= 1)
        s += __shfl_xor_sync(0xffffffffu, s, off);
    if (lane == 0) w[row] = 0.125f * s;
}

__global__ void minmax_kernel(const float* __restrict__ w, float* __restrict__ mm)
{
    __shared__ float smn[256], smx[256];
    const int b = blockIdx.x, tid = threadIdx.x;
    float mn = 1e30f, mx = -1e30f;
    for (int i = tid; i < QLEN; i += 256) {
        float v = w[b*QLEN + i];
        mn = fminf(mn, v); mx = fmaxf(mx, v);
    }
    smn[tid] = mn; smx[tid] = mx;
    __syncthreads();
    for (int s = 128; s > 0; s >>= 1) {
        if (tid < s) {
            smn[tid] = fminf(smn[tid], smn[tid + s]);
            smx[tid] = fmaxf(smx[tid], smx[tid + s]);
        }
        __syncthreads();
    }
    if (tid == 0) { mm[2*b] = smn[0]; mm[2*b + 1] = smx[0]; }
}

// ---------------- fused attention (packed fp32 / FFMA2 throughout) ----------
__global__ __launch_bounds__(128) void attn_kernel(
    const float* __restrict__ qb,
    const float* __restrict__ kk,
    const float* __restrict__ vv,
    const float* __restrict__ ipk,
    const float* __restrict__ ipv,
    const float* __restrict__ wbuf,
    const float* __restrict__ mm,
    float* __restrict__ hid)
{
    __shared__ __align__(16) float smem[TXTN*HDIM*2 + IPTN*HDIM*2];
    float* sK  = smem;
    float* sV  = smem + TXTN*HDIM;
    float* sIK = smem + 2*TXTN*HDIM;
    float* sIV = sIK + IPTN*HDIM;

    const int tid = threadIdx.x;
    const int b = blockIdx.z, h = blockIdx.y, q0 = blockIdx.x * 128;

    const size_t kvbase = ((size_t)b*TXTN)*HIDD + h*HDIM;
    for (int i = tid; i < TXTN*HDIM; i += 128) {
        int t = i >> 6, d = i & 63;
        sK[i] = kk[kvbase + (size_t)t*HIDD + d];
        sV[i] = vv[kvbase + (size_t)t*HIDD + d];
    }
    const size_t ipbase = ((size_t)b*IPTN)*HIDD + h*HDIM;
    for (int i = tid; i < IPTN*HDIM; i += 128) {
        int t = i >> 6, d = i & 63;
        sIK[i] = ipk[ipbase + (size_t)t*HIDD + d];
        sIV[i] = ipv[ipbase + (size_t)t*HIDD + d];
    }
    __syncthreads();

    const int qi = q0 + tid;

    u64 q2[32];
    {
        const ulonglong2* qp = (const ulonglong2*)(qb + ((size_t)b*QLEN + qi)*HIDD + h*HDIM);
        const u64 eighth = pack2(0.125f);
#pragma unroll
        for (int i = 0; i < 16; i++) {
            ulonglong2 v = qp[i];
            q2[2*i]   = v.x;
            q2[2*i+1] = v.y;
        }
#pragma unroll
        for (int i = 0; i < 32; i++) mul2(q2[i], eighth);
    }

    float m = -1e30f, l = 0.f;
    u64 o2[32];
#pragma unroll
    for (int i = 0; i < 32; i++) o2[i] = 0ULL;

    for (int t = 0; t < TXTN; t++) {
        const u64* kp = (const u64*)(sK + t*HDIM);
        u64 a = 0ULL;
#pragma unroll
        for (int i = 0; i < 32; i++) fma2(a, q2[i], kp[i]);
        float lo, hi; unpack2(lo, hi, a);
        float s = lo + hi;
        if (s > m) {
            float c = __expf(m - s);
            l *= c;
            u64 cc = pack2(c);
#pragma unroll
            for (int i = 0; i < 32; i++) mul2(o2[i], cc);
            m = s;
        }
        float p = __expf(s - m);
        l += p;
        u64 pp = pack2(p);
        const u64* vp = (const u64*)(sV + t*HDIM);
#pragma unroll
        for (int i = 0; i < 32; i++) fma2(o2[i], pp, vp[i]);
    }
    const float inv_l = 1.f / l;

    float sip[IPTN];
#pragma unroll
    for (int t = 0; t < IPTN; t++) {
        const u64* kp = (const u64*)(sIK + t*HDIM);
        u64 a = 0ULL;
#pragma unroll
        for (int i = 0; i < 32; i++) fma2(a, q2[i], kp[i]);
        float lo, hi; unpack2(lo, hi, a);
        sip[t] = lo + hi;
    }
    const int gr = qi >> 6, gc = qi & 63;
    const int region = (gr < 32) ? ((gc < 32) ? 0 : -1)
                                 : ((gc >= 32) ? 1 : -1);
    if (region == 0) { sip[4] = sip[5] = sip[6] = sip[7] = -1e30f; }
    else if (region == 1) { sip[0] = sip[1] = sip[2] = sip[3] = -1e30f; }

    float m2 = -1e30f;
#pragma unroll
    for (int t = 0; t < IPTN; t++) m2 = fmaxf(m2, sip[t]);
    float p2[IPTN], sum2 = 0.f;
#pragma unroll
    for (int t = 0; t < IPTN; t++) { p2[t] = __expf(sip[t] - m2); sum2 += p2[t]; }

    const float wv  = wbuf[b*QLEN + qi];
    const float wmn = mm[2*b], wmx = mm[2*b + 1];
    float aw = (wv - wmn) / (wmx - wmn);
    aw = (aw < 0.3f) ? 0.f : aw;
    aw *= 0.5f;
    if (region >= 0) aw = aw * 2.f + 1.f;
    const float coeff = aw / sum2;

    u64 pp2[IPTN];
#pragma unroll
    for (int t = 0; t < IPTN; t++) pp2[t] = pack2(p2[t]);
    const u64 invl2 = pack2(inv_l);
    const u64 co2   = pack2(coeff);

    __syncthreads();
    float* so = smem;
    const u64* iv = (const u64*)sIV;
#pragma unroll
    for (int i = 0; i < 32; i++) {
        u64 ipa = 0ULL;
#pragma unroll
        for (int t = 0; t < IPTN; t++) fma2(ipa, pp2[t], iv[t*32 + i]);
        mul2(o2[i], invl2);
        fma2(o2[i], co2, ipa);
        float lo, hi; unpack2(lo, hi, o2[i]);
        so[tid*68 + 2*i]     = roundtf(lo);
        so[tid*68 + 2*i + 1] = roundtf(hi);
    }
    __syncthreads();

    float* outp = hid + ((size_t)b*QLEN + q0)*HIDD + h*HDIM;
    for (int i4 = tid; i4 < 128*16; i4 += 128) {
        int r = i4 >> 4, c = i4 & 15;
        float4 v = *(const float4*)(so + r*68 + c*4);
        *(float4*)(outp + (size_t)r*HIDD + c*4) = v;
    }
}

// ---------------- host launcher ----------------
extern "C" void kernel_launch(void* const* d_in, const int* in_sizes, int n_in,
                              void* d_out, int out_size)
{
    const float* hs     = (const float*)d_in[0];
    const float* enc    = (const float*)d_in[1];
    const float* Wq     = (const float*)d_in[2];
    const float* Wk     = (const float*)d_in[3];
    const float* Wv     = (const float*)d_in[4];
    const float* Wo     = (const float*)d_in[5];
    const float* bo     = (const float*)d_in[6];
    const float* q_down = (const float*)d_in[7];
    const float* q_up   = (const float*)d_in[8];
    const float* k_down = (const float*)d_in[9];
    const float* k_up   = (const float*)d_in[10];
    const float* v_down = (const float*)d_in[11];
    const float* v_up   = (const float*)d_in[12];
    const float* o_down = (const float*)d_in[13];
    const float* o_up   = (const float*)d_in[14];
    const float* Wk_ip  = (const float*)d_in[15];
    const float* Wv_ip  = (const float*)d_in[16];
    float* out = (float*)d_out;

    float *pWq, *pWqR, *pWkR, *pWvR, *pWoR, *pq, *phid, *pkk, *pvv, *pipk, *pipv;
    float *pehs, *pip, *pipsum, *pipkS, *pwqs, *pw, *pmm;
    cudaGetSymbolAddress((void**)&pWq,   g_Wq);
    cudaGetSymbolAddress((void**)&pWqR,  g_WqR);
    cudaGetSymbolAddress((void**)&pWkR,  g_WkR);
    cudaGetSymbolAddress((void**)&pWvR,  g_WvR);
    cudaGetSymbolAddress((void**)&pWoR,  g_WoR);
    cudaGetSymbolAddress((void**)&pq,    g_q);
    cudaGetSymbolAddress((void**)&phid,  g_hid);
    cudaGetSymbolAddress((void**)&pkk,   g_kk);
    cudaGetSymbolAddress((void**)&pvv,   g_vv);
    cudaGetSymbolAddress((void**)&pipk,  g_ipk);
    cudaGetSymbolAddress((void**)&pipv,  g_ipv);
    cudaGetSymbolAddress((void**)&pehs,  g_ehs);
    cudaGetSymbolAddress((void**)&pip,   g_ip);
    cudaGetSymbolAddress((void**)&pipsum,g_ipsum);
    cudaGetSymbolAddress((void**)&pipkS, g_ipkS);
    cudaGetSymbolAddress((void**)&pwqs,  g_wqs);
    cudaGetSymbolAddress((void**)&pw,    g_w);
    cudaGetSymbolAddress((void**)&pmm,   g_mm);

    // side stream + fork/join events: created ONCE, before any capture of this
    // function body can be in flight on later calls (host objects, not device mem)
    static cudaStream_t s2 = nullptr;
    static cudaEvent_t eO = nullptr, eF = nullptr, eS = nullptr;
    if (s2 == nullptr) {
        cudaStreamCreateWithFlags(&s2, cudaStreamNonBlocking);
        cudaEventCreateWithFlags(&eO, cudaEventDisableTiming);
        cudaEventCreateWithFlags(&eF, cudaEventDisableTiming);
        cudaEventCreateWithFlags(&eS, cudaEventDisableTiming);
    }

    // ---- fork point: side stream must join the capture BEFORE any s2 work ----
    cudaEventRecord(eO, 0);
    cudaStreamWaitEvent(s2, eO, 0);

    // ---- main stream: weight fusion, then the big Q-GEMM ----
    const int fuse_elems = 2*HIDD*HIDD + 2*CDIM*HIDD;
    fuse_all_kernel<<<(fuse_elems + 255)/256, 256>>>(
        Wq, q_down, q_up, Wk, k_down, k_up, Wv, v_down, v_up, Wo, o_down, o_up,
        pWq, pWqR, pWkR, pWvR, pWoR);
    cudaEventRecord(eF, 0);

    // ---- side stream: pack -> merged enc/ip projections -> exact fp32 gate ----
    pack_enc_kernel<<<((NB*TXTN + NB*IPTN)*CDIM + 255)/256, 256, 0, s2>>>(enc, pehs, pip);
    cudaStreamWaitEvent(s2, eF, 0);
    gemm_encip<<<dim3(HIDD/128, 4, 2), 128, 0, s2>>>(
        pehs, pip, pWkR, pWvR, Wk_ip, Wv_ip, pkk, pvv, pipk, pipv);
    ipsum_kernel<<<(NB*CDIM + 255)/256, 256, 0, s2>>>(pip, pipsum);
    colvec_kernel<<<dim3(HIDD/256, NB), 256, 0, s2>>>(pipsum, Wk_ip, pipkS);
    wqs_matvec_kernel<<<dim3(HIDD/8, NB), 256, 0, s2>>>(pWq, pipkS, pwqs);
    wsum_kernel<<<NB*QLEN/8, 256, 0, s2>>>(hs, pwqs, pw);
    minmax_kernel<<<NB, 256, 0, s2>>>(pw, pmm);
    cudaEventRecord(eS, s2);

    // ---- main stream: Q-GEMM runs concurrently with the whole side chain ----
    gemm_tf32<true, false><<<dim3(HIDD/128, NB*QLEN/128), 128>>>(
        hs, pWqR, pq, nullptr, NB*QLEN, HIDD, HIDD);

    // join, then attention + output projection
    cudaStreamWaitEvent(0, eS, 0);
    attn_kernel<<<dim3(QLEN/128, NHEAD, NB), 128>>>(pq, pkk, pvv, pipk, pipv, pw, pmm, phid);
    gemm_tf32<false, false><<<dim3(HIDD/128, NB*QLEN/128), 128>>>(
        phid, pWoR, out, bo, NB*QLEN, HIDD, HIDD);
}

// round 11
// speedup vs baseline: 4.5335x; 1.2981x over previous
#include <cuda_runtime.h>
#include <cuda_fp16.h>
#include <cstdint>
#include <cstring>

#define NB    4
#define QLEN  4096
#define HIDD  1024
#define NHEAD 16
#define HDIM  64
#define TXTN  77
#define IPTN  8
#define CDIM  768
#define ENCR  85   // TXT + IPT

// ---------------- scratch (no allocation allowed) ----------------
__device__ float  g_Wq  [HIDD*HIDD];   // fp32-exact (gate path)
__device__ __half g_WqT [HIDD*HIDD];   // fp16, TRANSPOSED [N,K]
__device__ __half g_WoT [HIDD*HIDD];   // fp16, TRANSPOSED [N,K]
__device__ float  g_WkR [CDIM*HIDD];
__device__ float  g_WvR [CDIM*HIDD];
__device__ __half g_hsH [NB*QLEN*HIDD];  // hs converted to half
__device__ float  g_q   [NB*QLEN*HIDD];
__device__ __half g_hidH[NB*QLEN*HIDD];  // attention output, half
__device__ float  g_kk  [NB*TXTN*HIDD];
__device__ float  g_vv  [NB*TXTN*HIDD];
__device__ float  g_ipk [NB*IPTN*HIDD];
__device__ float  g_ipv [NB*IPTN*HIDD];
__device__ float  g_ehs [NB*TXTN*CDIM];   // pre-rounded to tf32
__device__ float  g_ip  [NB*IPTN*CDIM];   // exact (gate path reads it)
__device__ float  g_ipsum[NB*CDIM];
__device__ float  g_ipkS[NB*HIDD];
__device__ float  g_wqs [NB*HIDD];
__device__ float  g_w   [NB*QLEN];
__device__ float  g_mm  [2*NB];

typedef unsigned long long u64;

__device__ __forceinline__ uint32_t h2u(__half2 h) {
    uint32_t u;
    memcpy(&u, &h, 4);
    return u;
}

__device__ __forceinline__ uint32_t f2tf(float x) {
    uint32_t r;
    asm("cvt.rna.tf32.f32 %0, %1;" : "=r"(r) : "f"(x));
    return r;
}
__device__ __forceinline__ float roundtf(float x) {
    return __uint_as_float(f2tf(x));
}
// ---- packed fp32 (FFMA2) helpers ----
__device__ __forceinline__ void fma2(u64& d, u64 a, u64 b) {
    asm("fma.rn.f32x2 %0, %1, %2, %0;" : "+l"(d) : "l"(a), "l"(b));
}
__device__ __forceinline__ void mul2(u64& d, u64 c) {
    asm("mul.rn.f32x2 %0, %0, %1;" : "+l"(d) : "l"(c));
}
__device__ __forceinline__ u64 pack2(float x) {
    u64 r; asm("mov.b64 %0, {%1, %1};" : "=l"(r) : "f"(x)); return r;
}
__device__ __forceinline__ void unpack2(float& lo, float& hi, u64 v) {
    asm("mov.b64 {%0, %1}, %2;" : "=f"(lo), "=f"(hi) : "l"(v));
}

__device__ __forceinline__ void cp16g(uint32_t s, const void* g) {
    asm volatile("cp.async.ca.shared.global [%0], [%1], 16;" :: "r"(s), "l"(g));
}
__device__ __forceinline__ void cp_commit() {
    asm volatile("cp.async.commit_group;");
}
template<int N_> __device__ __forceinline__ void cp_wait() {
    asm volatile("cp.async.wait_group %0;" :: "n"(N_));
}

// ================= FP16 tensor-core GEMM: C[M,N] = A[M,K] @ Bt[N,K]^T ========
// mma.sync.m16n8k16 f16 (2x tf32 rate). CTA 128x128, BK=64 halves, 4 warps.
// A, Bt are __half; C fp32 (+bias). M%128==0, N%128==0, K%64==0.
#define HPAD 72                       // halves per smem row (conflict-free frags)
#define GH_STAGE (128*HPAD*2)         // 18432 B per tile buffer
#define GH_SMEM  (4*GH_STAGE)         // A0,A1,B0,B1 = 73728 B

__device__ __forceinline__ void mma_fp16(float* c, const uint32_t* a, const uint32_t* b) {
    asm volatile("mma.sync.aligned.m16n8k16.row.col.f32.f16.f16.f32 "
        "{%0,%1,%2,%3}, {%4,%5,%6,%7}, {%8,%9}, {%0,%1,%2,%3};"
        : "+f"(c[0]), "+f"(c[1]), "+f"(c[2]), "+f"(c[3])
        : "r"(a[0]), "r"(a[1]), "r"(a[2]), "r"(a[3]), "r"(b[0]), "r"(b[1]));
}

__global__ __launch_bounds__(128) void gemm_fp16(
    const __half* __restrict__ A, const __half* __restrict__ Bt,
    float* __restrict__ C, const float* __restrict__ bias, int K, int N)
{
    extern __shared__ __align__(16) char sm[];
    const uint32_t sA = (uint32_t)__cvta_generic_to_shared(sm);
    const uint32_t sB = sA + 2*GH_STAGE;

    const int tid  = threadIdx.x;
    const int lane = tid & 31;
    const int warp = tid >> 5;
    const int wm = (warp >> 1) * 64;
    const int wn = (warp & 1) * 64;
    const int row0 = blockIdx.y * 128;
    const int n0   = blockIdx.x * 128;

    const __half* Ab = A  + (size_t)row0 * K;
    const __half* Bb = Bt + (size_t)n0 * K;

    float acc[4][8][4];
#pragma unroll
    for (int i = 0; i < 4; i++)
#pragma unroll
        for (int j = 0; j < 8; j++)
#pragma unroll
            for (int r = 0; r < 4; r++) acc[i][j][r] = 0.f;

    auto load_stage = [&](int s, int buf) {
        const uint32_t ab = sA + (uint32_t)buf * GH_STAGE;
        const uint32_t bb = sB + (uint32_t)buf * GH_STAGE;
        const int k0 = s * 64;                 // halves
#pragma unroll
        for (int i = 0; i < 8; i++) {
            int c = tid + 128 * i;             // 1024 chunks of 16B (128 rows x 8)
            int r = c >> 3, cc = c & 7;
            cp16g(ab + (uint32_t)(r * (HPAD*2) + cc * 16),
                  Ab + (size_t)r * K + k0 + cc * 8);
            cp16g(bb + (uint32_t)(r * (HPAD*2) + cc * 16),
                  Bb + (size_t)r * K + k0 + cc * 8);
        }
    };

    const int nstage = K / 64;
    load_stage(0, 0);
    cp_commit();

    for (int s = 0; s < nstage; s++) {
        const int buf = s & 1;
        if (s + 1 < nstage) {
            load_stage(s + 1, buf ^ 1);
            cp_commit();
            cp_wait<1>();
        } else {
            cp_wait<0>();
        }
        __syncthreads();

        const uint32_t ab = sA + (uint32_t)buf * GH_STAGE;
        const uint32_t bb = sB + (uint32_t)buf * GH_STAGE;
        const int g = lane >> 2, t = lane & 3;

#pragma unroll
        for (int ks = 0; ks < 64; ks += 16) {
            uint32_t af[4][4];
#pragma unroll
            for (int im = 0; im < 4; im++) {
                uint32_t base = ab + (uint32_t)((wm + im*16 + g) * (HPAD*2) + (ks + 2*t) * 2);
                asm volatile("ld.shared.b32 %0, [%1];"      : "=r"(af[im][0]) : "r"(base));
                asm volatile("ld.shared.b32 %0, [%1];"      : "=r"(af[im][1]) : "r"(base + 8*(HPAD*2)));
                asm volatile("ld.shared.b32 %0, [%1];"      : "=r"(af[im][2]) : "r"(base + 16));
                asm volatile("ld.shared.b32 %0, [%1];"      : "=r"(af[im][3]) : "r"(base + 8*(HPAD*2) + 16));
            }
            uint32_t bf[8][2];
#pragma unroll
            for (int jn = 0; jn < 8; jn++) {
                uint32_t base = bb + (uint32_t)((wn + jn*8 + g) * (HPAD*2) + (ks + 2*t) * 2);
                asm volatile("ld.shared.b32 %0, [%1];" : "=r"(bf[jn][0]) : "r"(base));
                asm volatile("ld.shared.b32 %0, [%1];" : "=r"(bf[jn][1]) : "r"(base + 16));
            }
#pragma unroll
            for (int im = 0; im < 4; im++)
#pragma unroll
                for (int jn = 0; jn < 8; jn++)
                    mma_fp16(acc[im][jn], af[im], bf[jn]);
        }
        __syncthreads();
    }

#pragma unroll
    for (int im = 0; im < 4; im++) {
#pragma unroll
        for (int jn = 0; jn < 8; jn++) {
            int r = row0 + wm + im*16 + (lane >> 2);
            int c = n0 + wn + jn*8 + 2*(lane & 3);
            float2 v0 = make_float2(acc[im][jn][0], acc[im][jn][1]);
            float2 v1 = make_float2(acc[im][jn][2], acc[im][jn][3]);
            if (bias) {
                float2 bv = *(const float2*)(bias + c);
                v0.x += bv.x; v0.y += bv.y;
                v1.x += bv.x; v1.y += bv.y;
            }
            *(float2*)(C + (size_t)r*N + c)       = v0;
            *(float2*)(C + (size_t)(r + 8)*N + c) = v1;
        }
    }
}

// ---------------- hs -> half (one-time convert) ----------------
__global__ void hs2h_kernel(const float* __restrict__ hs, __half* __restrict__ out)
{
    int i = (blockIdx.x * 256 + threadIdx.x) * 4;
    float4 v = *(const float4*)(hs + i);
    __half2 h0 = __floats2half2_rn(v.x, v.y);
    __half2 h1 = __floats2half2_rn(v.z, v.w);
    uint2 w = make_uint2(h2u(h0), h2u(h1));
    *(uint2*)(out + i) = w;
}

// ---------------- fuse + transpose (Wq / Wo): out half [N,K] ----------------
__global__ __launch_bounds__(256) void fuse_t_kernel(
    const float* __restrict__ W, const float* __restrict__ dn,
    const float* __restrict__ up, __half* __restrict__ outT,
    float* __restrict__ outF)
{
    __shared__ float t[32][33];
    const int bx = blockIdx.x, by = blockIdx.y;
    const int tx = threadIdx.x & 31, ty = threadIdx.x >> 5;   // (32, 8)
#pragma unroll
    for (int i = 0; i < 4; i++) {
        int rr = by * 32 + ty + 8 * i;
        int cc = bx * 32 + tx;
        float acc = W[rr * HIDD + cc];
#pragma unroll
        for (int j = 0; j < 4; j++)
            acc = fmaf(dn[rr * 4 + j], up[j * HIDD + cc], acc);
        if (outF) outF[rr * HIDD + cc] = acc;
        t[ty + 8 * i][tx] = acc;
    }
    __syncthreads();
#pragma unroll
    for (int i = 0; i < 4; i++) {
        int rr = by * 32 + tx;             // original row (K)
        int cc = bx * 32 + ty + 8 * i;     // original col (N)
        outT[(size_t)cc * HIDD + rr] = __float2half_rn(t[tx][ty + 8 * i]);
    }
}

// ---------------- fold LoRA into Wk/Wv (untransposed, tf32-rounded) ----------
__global__ void fuse_kv_kernel(
    const float* __restrict__ Wk, const float* __restrict__ kd, const float* __restrict__ ku,
    const float* __restrict__ Wv, const float* __restrict__ vd, const float* __restrict__ vu,
    float* __restrict__ oWkR, float* __restrict__ oWvR)
{
    const int NK = CDIM*HIDD;
    int idx = blockIdx.x * 256 + threadIdx.x;
    const float *W, *dn, *up;
    float* oR;
    int li;
    if (idx < NK)        { W=Wk; dn=kd; up=ku; oR=oWkR; li=idx; }
    else if (idx < 2*NK) { W=Wv; dn=vd; up=vu; oR=oWvR; li=idx-NK; }
    else return;
    int r = li >> 10, c = li & 1023;
    float acc = W[li];
#pragma unroll
    for (int j = 0; j < 4; j++)
        acc = fmaf(dn[r*4 + j], up[j*HIDD + c], acc);
    oR[li] = roundtf(acc);
}

// ---------------- pack encoder slices contiguous ----------------
__global__ void pack_enc_kernel(const float* __restrict__ enc,
                                float* __restrict__ ehs,
                                float* __restrict__ ipb)
{
    int idx = blockIdx.x * 256 + threadIdx.x;
    const int n1 = NB*TXTN*CDIM;
    const int n2 = NB*IPTN*CDIM;
    if (idx < n1) {
        int b = idx / (TXTN*CDIM);
        int rem = idx - b*(TXTN*CDIM);
        int t = rem / CDIM, c = rem - t*CDIM;
        ehs[idx] = roundtf(enc[((size_t)b*ENCR + t)*CDIM + c]);
    } else if (idx < n1 + n2) {
        int k = idx - n1;
        int b = k / (IPTN*CDIM);
        int rem = k - b*(IPTN*CDIM);
        int t = rem / CDIM, c = rem - t*CDIM;
        ipb[k] = enc[((size_t)b*ENCR + TXTN + t)*CDIM + c];
    }
}

// ================= mma.sync TF32 GEMM body (small enc/ip projections) =======
#define APAD 20
#define BPAD 136

__device__ __forceinline__ void mma_tf32(float* c, const uint32_t* a, const uint32_t* b) {
    asm volatile("mma.sync.aligned.m16n8k8.row.col.f32.tf32.tf32.f32 "
        "{%0,%1,%2,%3}, {%4,%5,%6,%7}, {%8,%9}, {%0,%1,%2,%3};"
        : "+f"(c[0]), "+f"(c[1]), "+f"(c[2]), "+f"(c[3])
        : "r"(a[0]), "r"(a[1]), "r"(a[2]), "r"(a[3]), "r"(b[0]), "r"(b[1]));
}
__device__ __forceinline__ uint32_t ldfragc(const float* p) {
    return f2tf(*p);
}

__device__ __forceinline__ void gemm_body_tf32(
    const float* __restrict__ A, const float* __restrict__ B,
    float* __restrict__ C, int M, int N, int K, int bx, int by)
{
    __shared__ float As[2][128*APAD];
    __shared__ float Bs[2][16*BPAD];

    const int tid  = threadIdx.x;
    const int lane = tid & 31;
    const int warp = tid >> 5;
    const int wm = (warp >> 1) * 64;
    const int wn = (warp & 1) * 64;

    const float* Bg = B + bx * 128;

    const int a_colv = tid & 3;
    const int a_rowb = tid >> 2;
    const int b_colv = tid & 31;
    const int b_rowb = tid >> 5;

    const uint32_t as0 = (uint32_t)__cvta_generic_to_shared(&As[0][0]);
    const uint32_t bs0 = (uint32_t)__cvta_generic_to_shared(&Bs[0][0]);

    float acc[4][8][4];
#pragma unroll
    for (int i = 0; i < 4; i++)
#pragma unroll
        for (int j = 0; j < 8; j++)
#pragma unroll
            for (int r = 0; r < 4; r++) acc[i][j][r] = 0.f;

    auto load_stage = [&](int k0, int buf) {
        uint32_t asb = as0 + (uint32_t)buf * (128*APAD*4);
        uint32_t bsb = bs0 + (uint32_t)buf * (16*BPAD*4);
#pragma unroll
        for (int i = 0; i < 4; i++) {
            int row = a_rowb + i*32;
            int rg = by*128 + row; if (rg > M-1) rg = M-1;
            cp16g(asb + (uint32_t)(row*APAD + a_colv*4)*4,
                 A + (size_t)rg*K + k0 + a_colv*4);
        }
#pragma unroll
        for (int i = 0; i < 4; i++) {
            int row = b_rowb + i*4;
            cp16g(bsb + (uint32_t)(row*BPAD + b_colv*4)*4,
                 Bg + (size_t)(k0 + row)*N + b_colv*4);
        }
    };

    const int nstage = K / 16;
    load_stage(0, 0);
    cp_commit();

    int buf = 0;
    for (int s = 0; s < nstage; s++) {
        if (s + 1 < nstage) {
            load_stage((s + 1)*16, buf ^ 1);
            cp_commit();
            cp_wait<1>();
        } else {
            cp_wait<0>();
        }
        __syncthreads();

        const float* as = As[buf];
        const float* bs = Bs[buf];
#pragma unroll
        for (int ks = 0; ks < 16; ks += 8) {
            uint32_t af[4][4];
#pragma unroll
            for (int im = 0; im < 4; im++) {
                const float* ap = as + (wm + im*16 + (lane >> 2))*APAD + ks + (lane & 3);
                af[im][0] = ldfragc(ap);
                af[im][1] = ldfragc(ap + 8*APAD);
                af[im][2] = ldfragc(ap + 4);
                af[im][3] = ldfragc(ap + 8*APAD + 4);
            }
            uint32_t bf[8][2];
#pragma unroll
            for (int jn = 0; jn < 8; jn++) {
                const float* bp = bs + (ks + (lane & 3))*BPAD + wn + jn*8 + (lane >> 2);
                bf[jn][0] = ldfragc(bp);
                bf[jn][1] = ldfragc(bp + 4*BPAD);
            }
#pragma unroll
            for (int im = 0; im < 4; im++)
#pragma unroll
                for (int jn = 0; jn < 8; jn++)
                    mma_tf32(acc[im][jn], af[im], bf[jn]);
        }
        __syncthreads();
        buf ^= 1;
    }

#pragma unroll
    for (int im = 0; im < 4; im++) {
#pragma unroll
        for (int jn = 0; jn < 8; jn++) {
            int r = by*128 + wm + im*16 + (lane >> 2);
            int c = bx*128 + wn + jn*8 + 2*(lane & 3);
            float2 v0 = make_float2(acc[im][jn][0], acc[im][jn][1]);
            float2 v1 = make_float2(acc[im][jn][2], acc[im][jn][3]);
            if (r < M)     *(float2*)(C + (size_t)r*N + c)       = v0;
            if (r + 8 < M) *(float2*)(C + (size_t)(r + 8)*N + c) = v1;
        }
    }
}

// Merged enc-K/V + ip-K/V projections: grid (8, 4, 2)
__global__ __launch_bounds__(128, 2) void gemm_encip(
    const float* __restrict__ ehs, const float* __restrict__ ipb,
    const float* __restrict__ WkR, const float* __restrict__ WvR,
    const float* __restrict__ Wk_ip, const float* __restrict__ Wv_ip,
    float* __restrict__ kk, float* __restrict__ vv,
    float* __restrict__ ipk, float* __restrict__ ipv)
{
    const int y = blockIdx.y, z = blockIdx.z;
    const float *A, *B; float* C; int M, by;
    if (y < 3) { A = ehs; M = NB*TXTN; by = y; B = z ? WvR  : WkR;   C = z ? vv  : kk;  }
    else       { A = ipb; M = NB*IPTN; by = 0; B = z ? Wv_ip : Wk_ip; C = z ? ipv : ipk; }
    gemm_body_tf32(A, B, C, M, HIDD, CDIM, blockIdx.x, by);
}

// ---------------- exact fp32 gate path ----------------
__global__ void ipsum_kernel(const float* __restrict__ ip, float* __restrict__ out)
{
    int idx = blockIdx.x * 256 + threadIdx.x;
    if (idx >= NB * CDIM) return;
    int b = idx / CDIM, c = idx - b*CDIM;
    float s = 0.f;
#pragma unroll
    for (int t = 0; t < IPTN; t++)
        s += ip[((size_t)b*IPTN + t)*CDIM + c];
    out[idx] = s;
}

__global__ __launch_bounds__(256) void colvec_kernel(
    const float* __restrict__ s, const float* __restrict__ W,
    float* __restrict__ out)
{
    __shared__ float ss[CDIM];
    const int b = blockIdx.y;
    const int j = blockIdx.x * 256 + threadIdx.x;
    for (int i = threadIdx.x; i < CDIM; i += 256) ss[i] = s[b*CDIM + i];
    __syncthreads();
    float acc = 0.f;
#pragma unroll 8
    for (int i = 0; i < CDIM; i++)
        acc = fmaf(ss[i], W[(size_t)i*HIDD + j], acc);
    out[b*HIDD + j] = acc;
}

__global__ __launch_bounds__(256) void wqs_matvec_kernel(
    const float* __restrict__ W, const float* __restrict__ s,
    float* __restrict__ v)
{
    __shared__ float sv[HIDD];
    const int b = blockIdx.y;
    for (int i = threadIdx.x; i < HIDD; i += 256) sv[i] = s[b*HIDD + i];
    __syncthreads();
    const int warp = threadIdx.x >> 5, lane = threadIdx.x & 31;
    const int row = blockIdx.x * 8 + warp;
    const float* wr = W + (size_t)row * HIDD;
    float acc = 0.f;
#pragma unroll
    for (int i = 0; i < 32; i++)
        acc = fmaf(wr[lane + 32*i], sv[lane + 32*i], acc);
#pragma unroll
    for (int off = 16; off > 0; off >>= 1)
        acc += __shfl_xor_sync(0xffffffffu, acc, off);
    if (lane == 0) v[b*HIDD + row] = acc;
}

__global__ __launch_bounds__(256) void wsum_kernel(const float* __restrict__ hs,
                                                   const float* __restrict__ vb,
                                                   float* __restrict__ w)
{
    __shared__ float sk[HIDD];
    const int row0 = blockIdx.x * 8;
    const int b = row0 / QLEN;
    for (int i = threadIdx.x; i < HIDD; i += 256) sk[i] = vb[b*HIDD + i];
    __syncthreads();
    const int warp = threadIdx.x >> 5, lane = threadIdx.x & 31;
    const int row = row0 + warp;
    const float* qr = hs + (size_t)row * HIDD;
    float s = 0.f;
#pragma unroll
    for (int i = 0; i < 32; i++)
        s = fmaf(qr[lane + 32*i], sk[lane + 32*i], s);
#pragma unroll
    for (int off = 16; off > 0; off >>= 1)
        s += __shfl_xor_sync(0xffffffffu, s, off);
    if (lane == 0) w[row] = 0.125f * s;
}

__global__ void minmax_kernel(const float* __restrict__ w, float* __restrict__ mm)
{
    __shared__ float smn[256], smx[256];
    const int b = blockIdx.x, tid = threadIdx.x;
    float mn = 1e30f, mx = -1e30f;
    for (int i = tid; i < QLEN; i += 256) {
        float v = w[b*QLEN + i];
        mn = fminf(mn, v); mx = fmaxf(mx, v);
    }
    smn[tid] = mn; smx[tid] = mx;
    __syncthreads();
    for (int s = 128; s > 0; s >>= 1) {
        if (tid < s) {
            smn[tid] = fminf(smn[tid], smn[tid + s]);
            smx[tid] = fmaxf(smx[tid], smx[tid + s]);
        }
        __syncthreads();
    }
    if (tid == 0) { mm[2*b] = smn[0]; mm[2*b + 1] = smx[0]; }
}

// ---------------- fused attention (packed fp32 / FFMA2; writes half) --------
__global__ __launch_bounds__(128) void attn_kernel(
    const float* __restrict__ qb,
    const float* __restrict__ kk,
    const float* __restrict__ vv,
    const float* __restrict__ ipk,
    const float* __restrict__ ipv,
    const float* __restrict__ wbuf,
    const float* __restrict__ mm,
    __half* __restrict__ hid)
{
    __shared__ __align__(16) float smem[TXTN*HDIM*2 + IPTN*HDIM*2];
    float* sK  = smem;
    float* sV  = smem + TXTN*HDIM;
    float* sIK = smem + 2*TXTN*HDIM;
    float* sIV = sIK + IPTN*HDIM;

    const int tid = threadIdx.x;
    const int b = blockIdx.z, h = blockIdx.y, q0 = blockIdx.x * 128;

    const size_t kvbase = ((size_t)b*TXTN)*HIDD + h*HDIM;
    for (int i = tid; i < TXTN*HDIM; i += 128) {
        int t = i >> 6, d = i & 63;
        sK[i] = kk[kvbase + (size_t)t*HIDD + d];
        sV[i] = vv[kvbase + (size_t)t*HIDD + d];
    }
    const size_t ipbase = ((size_t)b*IPTN)*HIDD + h*HDIM;
    for (int i = tid; i < IPTN*HDIM; i += 128) {
        int t = i >> 6, d = i & 63;
        sIK[i] = ipk[ipbase + (size_t)t*HIDD + d];
        sIV[i] = ipv[ipbase + (size_t)t*HIDD + d];
    }
    __syncthreads();

    const int qi = q0 + tid;

    u64 q2[32];
    {
        const ulonglong2* qp = (const ulonglong2*)(qb + ((size_t)b*QLEN + qi)*HIDD + h*HDIM);
        const u64 eighth = pack2(0.125f);
#pragma unroll
        for (int i = 0; i < 16; i++) {
            ulonglong2 v = qp[i];
            q2[2*i]   = v.x;
            q2[2*i+1] = v.y;
        }
#pragma unroll
        for (int i = 0; i < 32; i++) mul2(q2[i], eighth);
    }

    float m = -1e30f, l = 0.f;
    u64 o2[32];
#pragma unroll
    for (int i = 0; i < 32; i++) o2[i] = 0ULL;

    for (int t = 0; t < TXTN; t++) {
        const u64* kp = (const u64*)(sK + t*HDIM);
        u64 a = 0ULL;
#pragma unroll
        for (int i = 0; i < 32; i++) fma2(a, q2[i], kp[i]);
        float lo, hi; unpack2(lo, hi, a);
        float s = lo + hi;
        if (s > m) {
            float c = __expf(m - s);
            l *= c;
            u64 cc = pack2(c);
#pragma unroll
            for (int i = 0; i < 32; i++) mul2(o2[i], cc);
            m = s;
        }
        float p = __expf(s - m);
        l += p;
        u64 pp = pack2(p);
        const u64* vp = (const u64*)(sV + t*HDIM);
#pragma unroll
        for (int i = 0; i < 32; i++) fma2(o2[i], pp, vp[i]);
    }
    const float inv_l = 1.f / l;

    float sip[IPTN];
#pragma unroll
    for (int t = 0; t < IPTN; t++) {
        const u64* kp = (const u64*)(sIK + t*HDIM);
        u64 a = 0ULL;
#pragma unroll
        for (int i = 0; i < 32; i++) fma2(a, q2[i], kp[i]);
        float lo, hi; unpack2(lo, hi, a);
        sip[t] = lo + hi;
    }
    const int gr = qi >> 6, gc = qi & 63;
    const int region = (gr < 32) ? ((gc < 32) ? 0 : -1)
                                 : ((gc >= 32) ? 1 : -1);
    if (region == 0) { sip[4] = sip[5] = sip[6] = sip[7] = -1e30f; }
    else if (region == 1) { sip[0] = sip[1] = sip[2] = sip[3] = -1e30f; }

    float m2 = -1e30f;
#pragma unroll
    for (int t = 0; t < IPTN; t++) m2 = fmaxf(m2, sip[t]);
    float p2[IPTN], sum2 = 0.f;
#pragma unroll
    for (int t = 0; t < IPTN; t++) { p2[t] = __expf(sip[t] - m2); sum2 += p2[t]; }

    const float wv  = wbuf[b*QLEN + qi];
    const float wmn = mm[2*b], wmx = mm[2*b + 1];
    float aw = (wv - wmn) / (wmx - wmn);
    aw = (aw < 0.3f) ? 0.f : aw;
    aw *= 0.5f;
    if (region >= 0) aw = aw * 2.f + 1.f;
    const float coeff = aw / sum2;

    u64 pp2[IPTN];
#pragma unroll
    for (int t = 0; t < IPTN; t++) pp2[t] = pack2(p2[t]);
    const u64 invl2 = pack2(inv_l);
    const u64 co2   = pack2(coeff);

    __syncthreads();
    float* so = smem;
    const u64* iv = (const u64*)sIV;
#pragma unroll
    for (int i = 0; i < 32; i++) {
        u64 ipa = 0ULL;
#pragma unroll
        for (int t = 0; t < IPTN; t++) fma2(ipa, pp2[t], iv[t*32 + i]);
        mul2(o2[i], invl2);
        fma2(o2[i], co2, ipa);
        float lo, hi; unpack2(lo, hi, o2[i]);
        so[tid*68 + 2*i]     = lo;
        so[tid*68 + 2*i + 1] = hi;
    }
    __syncthreads();

    __half* outp = hid + ((size_t)b*QLEN + q0)*HIDD + h*HDIM;
    for (int i4 = tid; i4 < 128*16; i4 += 128) {
        int r = i4 >> 4, c = i4 & 15;
        float4 v = *(const float4*)(so + r*68 + c*4);
        __half2 h0 = __floats2half2_rn(v.x, v.y);
        __half2 h1 = __floats2half2_rn(v.z, v.w);
        uint2 w = make_uint2(h2u(h0), h2u(h1));
        *(uint2*)(outp + (size_t)r*HIDD + c*4) = w;
    }
}

// ---------------- host launcher ----------------
extern "C" void kernel_launch(void* const* d_in, const int* in_sizes, int n_in,
                              void* d_out, int out_size)
{
    const float* hs     = (const float*)d_in[0];
    const float* enc    = (const float*)d_in[1];
    const float* Wq     = (const float*)d_in[2];
    const float* Wk     = (const float*)d_in[3];
    const float* Wv     = (const float*)d_in[4];
    const float* Wo     = (const float*)d_in[5];
    const float* bo     = (const float*)d_in[6];
    const float* q_down = (const float*)d_in[7];
    const float* q_up   = (const float*)d_in[8];
    const float* k_down = (const float*)d_in[9];
    const float* k_up   = (const float*)d_in[10];
    const float* v_down = (const float*)d_in[11];
    const float* v_up   = (const float*)d_in[12];
    const float* o_down = (const float*)d_in[13];
    const float* o_up   = (const float*)d_in[14];
    const float* Wk_ip  = (const float*)d_in[15];
    const float* Wv_ip  = (const float*)d_in[16];
    float* out = (float*)d_out;

    float *pWq, *pWkR, *pWvR, *pq, *pkk, *pvv, *pipk, *pipv;
    float *pehs, *pip, *pipsum, *pipkS, *pwqs, *pw, *pmm;
    __half *pWqT, *pWoT, *phsH, *phidH;
    cudaGetSymbolAddress((void**)&pWq,   g_Wq);
    cudaGetSymbolAddress((void**)&pWqT,  g_WqT);
    cudaGetSymbolAddress((void**)&pWoT,  g_WoT);
    cudaGetSymbolAddress((void**)&pWkR,  g_WkR);
    cudaGetSymbolAddress((void**)&pWvR,  g_WvR);
    cudaGetSymbolAddress((void**)&phsH,  g_hsH);
    cudaGetSymbolAddress((void**)&pq,    g_q);
    cudaGetSymbolAddress((void**)&phidH, g_hidH);
    cudaGetSymbolAddress((void**)&pkk,   g_kk);
    cudaGetSymbolAddress((void**)&pvv,   g_vv);
    cudaGetSymbolAddress((void**)&pipk,  g_ipk);
    cudaGetSymbolAddress((void**)&pipv,  g_ipv);
    cudaGetSymbolAddress((void**)&pehs,  g_ehs);
    cudaGetSymbolAddress((void**)&pip,   g_ip);
    cudaGetSymbolAddress((void**)&pipsum,g_ipsum);
    cudaGetSymbolAddress((void**)&pipkS, g_ipkS);
    cudaGetSymbolAddress((void**)&pwqs,  g_wqs);
    cudaGetSymbolAddress((void**)&pw,    g_w);
    cudaGetSymbolAddress((void**)&pmm,   g_mm);

    // one-time host objects (created before first capture; persist)
    static cudaStream_t s2 = nullptr;
    static cudaEvent_t eO = nullptr, eF = nullptr, eS = nullptr;
    if (s2 == nullptr) {
        cudaStreamCreateWithFlags(&s2, cudaStreamNonBlocking);
        cudaEventCreateWithFlags(&eO, cudaEventDisableTiming);
        cudaEventCreateWithFlags(&eF, cudaEventDisableTiming);
        cudaEventCreateWithFlags(&eS, cudaEventDisableTiming);
        cudaFuncSetAttribute(gemm_fp16,
            cudaFuncAttributeMaxDynamicSharedMemorySize, GH_SMEM);
    }

    // ---- fork point: side stream joins the capture before any s2 work ----
    cudaEventRecord(eO, 0);
    cudaStreamWaitEvent(s2, eO, 0);

    // ---- main stream: hs->half, fuse+transpose Wq, then Q-GEMM (fp16 MMA) ----
    hs2h_kernel<<<NB*QLEN*HIDD/1024, 256>>>(hs, phsH);
    fuse_t_kernel<<<dim3(32, 32), 256>>>(Wq, q_down, q_up, pWqT, pWq);
    cudaEventRecord(eF, 0);
    gemm_fp16<<<dim3(HIDD/128, NB*QLEN/128), 128, GH_SMEM>>>(
        phsH, pWqT, pq, nullptr, HIDD, HIDD);

    // ---- side stream: Wo fuse+transpose, pack, enc/ip GEMMs, exact gate ----
    fuse_t_kernel<<<dim3(32, 32), 256, 0, s2>>>(Wo, o_down, o_up, pWoT, nullptr);
    pack_enc_kernel<<<((NB*TXTN + NB*IPTN)*CDIM + 255)/256, 256, 0, s2>>>(enc, pehs, pip);
    fuse_kv_kernel<<<(2*CDIM*HIDD + 255)/256, 256, 0, s2>>>(
        Wk, k_down, k_up, Wv, v_down, v_up, pWkR, pWvR);
    gemm_encip<<<dim3(HIDD/128, 4, 2), 128, 0, s2>>>(
        pehs, pip, pWkR, pWvR, Wk_ip, Wv_ip, pkk, pvv, pipk, pipv);
    ipsum_kernel<<<(NB*CDIM + 255)/256, 256, 0, s2>>>(pip, pipsum);
    colvec_kernel<<<dim3(HIDD/256, NB), 256, 0, s2>>>(pipsum, Wk_ip, pipkS);
    cudaStreamWaitEvent(s2, eF, 0);          // g_Wq (fp32) ready
    wqs_matvec_kernel<<<dim3(HIDD/8, NB), 256, 0, s2>>>(pWq, pipkS, pwqs);
    wsum_kernel<<<NB*QLEN/8, 256, 0, s2>>>(hs, pwqs, pw);
    minmax_kernel<<<NB, 256, 0, s2>>>(pw, pmm);
    cudaEventRecord(eS, s2);

    // ---- join, then attention (writes half) + output projection (fp16 MMA) ----
    cudaStreamWaitEvent(0, eS, 0);
    attn_kernel<<<dim3(QLEN/128, NHEAD, NB), 128>>>(pq, pkk, pvv, pipk, pipv, pw, pmm, phidH);
    gemm_fp16<<<dim3(HIDD/128, NB*QLEN/128), 128, GH_SMEM>>>(
        phidH, pWoT, out, bo, HIDD, HIDD);
}